// round 11
// baseline (speedup 1.0000x reference)
#include <cuda_runtime.h>
#include <cstdint>

typedef unsigned long long ull;

// ---------------------------------------------------------------------------
// Scratch buffers (device globals; no allocation allowed)
// ---------------------------------------------------------------------------
__device__ float g_w1 [786432];    // [4,12,128,128]
__device__ float g_c1 [1048576];   // [4,16,128,128]
__device__ float g_w2 [1048576];   // [4,64,64,64]
__device__ float g_c2 [1048576];   // [4,64,64,64]
__device__ float g_w3 [1048576];   // [4,256,32,32]
__device__ float g_c3 [1048576];   // [4,256,32,32]
__device__ float g_w4 [1048576];   // [4,1024,16,16]
__device__ float g_c4 [1048576];
__device__ float g_c5 [1048576];
__device__ float g_ic4[1048576];
__device__ float g_iw4[2097152];   // [4,512,32,32]
__device__ float g_ic3[1048576];   // [4,256,32,32]
__device__ float g_iw3[2097152];   // [4,128,64,64]
__device__ float g_ic2[1048576];   // [4,64,64,64]
__device__ float g_iw2[2097152];   // [4,32,128,128]
__device__ float g_ic1[1048576];   // [4,16,128,128]
__device__ float g_iw1[786432];    // [4,12,128,128]
__device__ float g_part[4194304];  // 4 x 1M partial-sum buffers

// ---------------------------------------------------------------------------
// f32x2 packed helpers (Blackwell FFMA2)
// ---------------------------------------------------------------------------
__device__ __forceinline__ ull pk(float x, float y) {
    ull r;
    asm("mov.b64 %0, {%1, %2};" : "=l"(r) : "f"(x), "f"(y));
    return r;
}
__device__ __forceinline__ void upk(float& x, float& y, ull v) {
    asm("mov.b64 {%0, %1}, %2;" : "=f"(x), "=f"(y) : "l"(v));
}
__device__ __forceinline__ void fma2(ull& d, ull a, ull b) {
    asm("fma.rn.f32x2 %0, %1, %2, %0;" : "+l"(d) : "l"(a), "l"(b));
}

// ---------------------------------------------------------------------------
// Haar DWT (standalone — only for the network input x)
// ---------------------------------------------------------------------------
__global__ void wt_k(const float* __restrict__ in, float* __restrict__ out,
                     int B, int C, int H, int W) {
    int Ho = H >> 1, Wo = W >> 1;
    int total = B * C * Ho * Wo;
    int i = blockIdx.x * blockDim.x + threadIdx.x;
    if (i >= total) return;
    int w = i % Wo;
    int h = (i / Wo) % Ho;
    int c = (i / (Wo * Ho)) % C;
    int b = i / (Wo * Ho * C);
    const float* p = in + ((size_t)(b * C + c) * H + 2 * h) * W + 2 * w;
    float a  = p[0], bb = p[1], cc = p[W], d = p[W + 1];
    float ll = 0.25f * (a + bb + cc + d);
    float hl = 0.5f  * (a + bb - cc - d);
    float lh = 0.5f  * (a - bb + cc - d);
    float hh = 0.5f  * (a - bb - cc + d);
    size_t ob = ((size_t)(b * 4 * C + 4 * c) * Ho + h) * Wo + w;
    size_t cs = (size_t)Ho * Wo;
    out[ob]          = ll;
    out[ob + cs]     = (hl + 1.f) * 0.5f;
    out[ob + 2 * cs] = (lh + 1.f) * 0.5f;
    out[ob + 3 * cs] = (hh + 1.f) * 0.5f;
}

// ---------------------------------------------------------------------------
// Fused IWT + skip-concat:  out[:, :Csrc] = skip;  out[:, Csrc:] = iwt(iwin)
// ---------------------------------------------------------------------------
__global__ void iwtcat_k(const float* __restrict__ iwin, const float* __restrict__ skip,
                         float* __restrict__ out, int B, int C4, int H, int W, int Ctot) {
    int C = C4 >> 2;
    int Csrc = Ctot - C;
    int HWo = 4 * H * W;
    int Niwt = B * C * H * W;
    int npc = HWo / 2;
    int Ncopy2 = B * Csrc * npc;
    int i = blockIdx.x * blockDim.x + threadIdx.x;
    if (i < Niwt) {
        int w = i % W;
        int h = (i / W) % H;
        int c = (i / (W * H)) % C;
        int b = i / (W * H * C);
        size_t ib = ((size_t)(b * C4 + 4 * c) * H + h) * W + w;
        size_t cs = (size_t)H * W;
        float v0 = iwin[ib];
        float v1 = 2.f * iwin[ib + cs]     - 1.f;
        float v2 = 2.f * iwin[ib + 2 * cs] - 1.f;
        float v3 = 2.f * iwin[ib + 3 * cs] - 1.f;
        float x00 = v0 + 0.5f * ( v1 + v2 + v3);
        float x01 = v0 + 0.5f * ( v1 - v2 - v3);
        float x10 = v0 + 0.5f * (-v1 + v2 - v3);
        float x11 = v0 + 0.5f * (-v1 - v2 + v3);
        int W2 = 2 * W;
        size_t ob = ((size_t)(b * Ctot + Csrc + c) * 2 * H + 2 * h) * W2 + 2 * w;
        out[ob]          = x00;
        out[ob + 1]      = x01;
        out[ob + W2]     = x10;
        out[ob + W2 + 1] = x11;
    } else {
        int j = i - Niwt;
        if (j >= Ncopy2) return;
        int pos = j % npc;
        int c   = (j / npc) % Csrc;
        int b   = j / (npc * Csrc);
        *(float2*)&out[((size_t)(b * Ctot) + c) * HWo + 2 * pos] =
            *(const float2*)&skip[((size_t)(b * Csrc) + c) * HWo + 2 * pos];
    }
}

// ---------------------------------------------------------------------------
// Partial direct 3x3 conv, pad=1 — oc-pair lane packing, 2x2 px per thread.
// NP oc-pairs per thread (small: high occupancy). Single-buffered input
// loads (TLP hides latency). blockIdx.z selects IC split; raw partials out.
// ---------------------------------------------------------------------------
template <int H, int W, int TPX, int TOC, int NP, int ICCHUNK>
__global__ void __launch_bounds__(TPX * TOC, 6)
convpart_k(const float* __restrict__ in, const float* __restrict__ wgt,
           float* __restrict__ part, int IC, int OC, int ics) {
    constexpr int NT    = TPX * TOC;
    constexpr int OCBLK = TOC * 2 * NP;
    constexpr int PAIRS = OCBLK / 2;
    constexpr int WN    = OCBLK * ICCHUNK * 9;
    constexpr int DN    = ICCHUNK * 9 * PAIRS;
    constexpr int TILESIMG = (H / 2) * (W / 2);

    __shared__ __align__(16) float  s_raw[2][WN];
    __shared__ __align__(16) float2 s_dup[DN];

    const int tid = threadIdx.x;
    const int tpx = tid % TPX;
    const int toc = tid / TPX;
    const int g   = blockIdx.x * TPX + tpx;
    const int img = g / TILESIMG;
    const int rem = g % TILESIMG;
    const int h0  = (rem / (W / 2)) * 2;
    const int w0  = (rem % (W / 2)) * 2;
    const int oc0 = blockIdx.y * OCBLK;
    const int z   = blockIdx.z;
    const int ic0 = z * ics;
    const int pairbase = toc * NP;

    const size_t HW = (size_t)H * W;
    const bool vr0 = (h0 > 0);
    const bool vr3 = (h0 + 2 < H);
    const bool lok = (w0 > 0);
    const bool rok = (w0 + 2 < W);

    ull acc[NP][2][2];
#pragma unroll
    for (int np = 0; np < NP; np++)
#pragma unroll
        for (int r = 0; r < 2; r++)
#pragma unroll
            for (int c = 0; c < 2; c++) acc[np][r][c] = pk(0.f, 0.f);

    const float* p0 = in + ((size_t)img * IC + ic0) * HW + (size_t)(h0 - 1) * W + (w0 - 1);
    const int nch = ics / ICCHUNK;

    // prologue: prefetch weight chunk 0 of this split
    for (int i = tid; i < WN; i += NT) {
        int o = i / (ICCHUNK * 9);
        int r = i - o * (ICCHUNK * 9);
        const float* src = wgt + ((size_t)(oc0 + o) * IC + ic0) * 9 + r;
        uint32_t dst = (uint32_t)__cvta_generic_to_shared(&s_raw[0][i]);
        asm volatile("cp.async.ca.shared.global [%0], [%1], 4;" :: "r"(dst), "l"(src));
    }
    asm volatile("cp.async.commit_group;" ::: "memory");

    for (int ch = 0; ch < nch; ch++) {
        asm volatile("cp.async.wait_group 0;" ::: "memory");
        __syncthreads();
        // pack weights into oc-pair float2
        for (int i = tid; i < DN; i += NT) {
            int pr = i % PAIRS;
            int t  = i / PAIRS;
            s_dup[i] = make_float2(s_raw[ch & 1][(2 * pr) * (ICCHUNK * 9) + t],
                                   s_raw[ch & 1][(2 * pr + 1) * (ICCHUNK * 9) + t]);
        }
        if (ch + 1 < nch) {
            const int icn = ic0 + (ch + 1) * ICCHUNK;
            for (int i = tid; i < WN; i += NT) {
                int o = i / (ICCHUNK * 9);
                int r = i - o * (ICCHUNK * 9);
                const float* src = wgt + ((size_t)(oc0 + o) * IC + icn) * 9 + r;
                uint32_t dst = (uint32_t)__cvta_generic_to_shared(&s_raw[(ch + 1) & 1][i]);
                asm volatile("cp.async.ca.shared.global [%0], [%1], 4;" :: "r"(dst), "l"(src));
            }
        }
        asm volatile("cp.async.commit_group;" ::: "memory");
        __syncthreads();

        const float* pb = p0 + (size_t)(ch * ICCHUNK) * HW;
#pragma unroll 2
        for (int kk = 0; kk < ICCHUNK; kk++) {
            const float* pc = pb + (size_t)kk * HW;
            ull bp[4][4];
#pragma unroll
            for (int ri = 0; ri < 4; ri++) {
                bool vr = (ri == 0) ? vr0 : (ri == 3) ? vr3 : true;
                const float* q = pc + ri * W;
                float2 m = make_float2(0.f, 0.f);
                float l = 0.f, r = 0.f;
                if (vr) {
                    m = *(const float2*)(q + 1);
                    if (lok) l = q[0];
                    if (rok) r = q[3];
                }
                bp[ri][0] = pk(l, l);
                bp[ri][1] = pk(m.x, m.x);
                bp[ri][2] = pk(m.y, m.y);
                bp[ri][3] = pk(r, r);
            }
            const float2* wrow = s_dup + (size_t)kk * 9 * PAIRS + pairbase;
#pragma unroll
            for (int ki = 0; ki < 3; ki++)
#pragma unroll
                for (int kj = 0; kj < 3; kj++) {
                    const int t = ki * 3 + kj;
                    ull wv[NP];
                    if constexpr ((NP % 2) == 0) {
#pragma unroll
                        for (int q2 = 0; q2 < NP / 2; q2++) {
                            ulonglong2 u = *(const ulonglong2*)&wrow[t * PAIRS + 2 * q2];
                            wv[2 * q2]     = u.x;
                            wv[2 * q2 + 1] = u.y;
                        }
                    } else {
#pragma unroll
                        for (int np = 0; np < NP; np++)
                            wv[np] = *(const ull*)&wrow[t * PAIRS + np];
                    }
#pragma unroll
                    for (int np = 0; np < NP; np++) {
                        fma2(acc[np][0][0], bp[ki][kj],         wv[np]);
                        fma2(acc[np][0][1], bp[ki][kj + 1],     wv[np]);
                        fma2(acc[np][1][0], bp[ki + 1][kj],     wv[np]);
                        fma2(acc[np][1][1], bp[ki + 1][kj + 1], wv[np]);
                    }
                }
        }
    }

    // ---- store raw partials ----
    float* pout = part + (size_t)z * 4 * OC * HW;
#pragma unroll
    for (int np = 0; np < NP; np++) {
        float a00, b00, a01, b01, a10, b10, a11, b11;
        upk(a00, b00, acc[np][0][0]); upk(a01, b01, acc[np][0][1]);
        upk(a10, b10, acc[np][1][0]); upk(a11, b11, acc[np][1][1]);
        const int ocA = oc0 + 2 * (pairbase + np);
        size_t baseA = ((size_t)(img * OC + ocA) * H + h0) * W + w0;
        size_t baseB = baseA + HW;
        *(float2*)&pout[baseA]     = make_float2(a00, a01);
        *(float2*)&pout[baseA + W] = make_float2(a10, a11);
        *(float2*)&pout[baseB]     = make_float2(b00, b01);
        *(float2*)&pout[baseB + W] = make_float2(b10, b11);
    }
}

// ---------------------------------------------------------------------------
// Combine four partial buffers: out = act(p0+p1+p2+p3 + bias (+skip))
// ---------------------------------------------------------------------------
template <bool RELU, bool ADD>
__global__ void combine4_k(const float* __restrict__ part, const float* __restrict__ bias,
                           const float* __restrict__ addsrc, float* __restrict__ out,
                           int OC, int HW, int total) {
    int i = (blockIdx.x * blockDim.x + threadIdx.x) * 2;
    if (i >= total) return;
    int c = (i / HW) % OC;
    float2 p0 = *(const float2*)&part[i];
    float2 p1 = *(const float2*)&part[total + i];
    float2 p2 = *(const float2*)&part[2 * (size_t)total + i];
    float2 p3 = *(const float2*)&part[3 * (size_t)total + i];
    float bv = bias[c];
    float v0 = (p0.x + p1.x) + (p2.x + p3.x) + bv;
    float v1 = (p0.y + p1.y) + (p2.y + p3.y) + bv;
    if (ADD) {
        float2 s = *(const float2*)&addsrc[i];
        v0 += s.x; v1 += s.y;
    }
    if (RELU) {
        v0 = (v0 >= 0.f) ? v0 : 0.2f * v0;
        v1 = (v1 >= 0.f) ? v1 : 0.2f * v1;
    }
    *(float2*)&out[i] = make_float2(v0, v1);
}

// ---------------------------------------------------------------------------
// Combine four partials + lrelu + fused Haar DWT of the result.
// ---------------------------------------------------------------------------
__global__ void combine4wt_k(const float* __restrict__ part, const float* __restrict__ bias,
                             float* __restrict__ out, float* __restrict__ wtout,
                             int OC, int H, int W, int total) {
    int HW = H * W;
    int nblk = total / 4;
    int i = blockIdx.x * blockDim.x + threadIdx.x;
    if (i >= nblk) return;
    int Wh = W / 2;
    int w2 = i % Wh;
    int h2 = (i / Wh) % (H / 2);
    int bc = i / (HW / 4);
    size_t base = (size_t)bc * HW + (size_t)(2 * h2) * W + 2 * w2;
    float bv = bias[bc % OC];
    float v00 = bv, v01 = bv, v10 = bv, v11 = bv;
#pragma unroll
    for (int z = 0; z < 4; z++) {
        const float* p = part + (size_t)z * total;
        float2 a = *(const float2*)&p[base];
        float2 b = *(const float2*)&p[base + W];
        v00 += a.x; v01 += a.y; v10 += b.x; v11 += b.y;
    }
    v00 = (v00 >= 0.f) ? v00 : 0.2f * v00;
    v01 = (v01 >= 0.f) ? v01 : 0.2f * v01;
    v10 = (v10 >= 0.f) ? v10 : 0.2f * v10;
    v11 = (v11 >= 0.f) ? v11 : 0.2f * v11;
    *(float2*)&out[base]     = make_float2(v00, v01);
    *(float2*)&out[base + W] = make_float2(v10, v11);

    float ll = 0.25f * (v00 + v01 + v10 + v11);
    float hl = 0.5f  * (v00 + v01 - v10 - v11);
    float lh = 0.5f  * (v00 - v01 + v10 - v11);
    float hh = 0.5f  * (v00 - v01 - v10 + v11);
    hl = (hl + 1.f) * 0.5f; lh = (lh + 1.f) * 0.5f; hh = (hh + 1.f) * 0.5f;
    int c = bc % OC, b_ = bc / OC;
    size_t cs = (size_t)HW / 4;
    size_t ob = ((size_t)(b_ * 4 * OC + 4 * c)) * cs + (size_t)h2 * Wh + w2;
    wtout[ob]          = ll;
    wtout[ob + cs]     = hl;
    wtout[ob + 2 * cs] = lh;
    wtout[ob + 3 * cs] = hh;
}

// ---------------------------------------------------------------------------
// Final: y = iwt(iw1[4,12,128,128]); out = 1x1 conv cfin @ y -> [4,3,256,256]
// ---------------------------------------------------------------------------
__global__ void final_k(const float* __restrict__ in, const float* __restrict__ cfin,
                        float* __restrict__ out, int B) {
    const int H = 128, W = 128;
    int total = B * H * W;
    int i = blockIdx.x * blockDim.x + threadIdx.x;
    if (i >= total) return;
    int w = i % W;
    int h = (i / W) % H;
    int b = i / (W * H);

    float y00[3], y01[3], y10[3], y11[3];
#pragma unroll
    for (int c = 0; c < 3; c++) {
        size_t ib = ((size_t)(b * 12 + 4 * c) * H + h) * W + w;
        size_t cs = (size_t)H * W;
        float v0 = in[ib];
        float v1 = 2.f * in[ib + cs]     - 1.f;
        float v2 = 2.f * in[ib + 2 * cs] - 1.f;
        float v3 = 2.f * in[ib + 3 * cs] - 1.f;
        y00[c] = v0 + 0.5f * ( v1 + v2 + v3);
        y01[c] = v0 + 0.5f * ( v1 - v2 - v3);
        y10[c] = v0 + 0.5f * (-v1 + v2 - v3);
        y11[c] = v0 + 0.5f * (-v1 - v2 + v3);
    }
    float m[9];
#pragma unroll
    for (int j = 0; j < 9; j++) m[j] = cfin[j];

    const int HO = 256, WO = 256;
#pragma unroll
    for (int o = 0; o < 3; o++) {
        float o00 = m[o*3+0]*y00[0] + m[o*3+1]*y00[1] + m[o*3+2]*y00[2];
        float o01 = m[o*3+0]*y01[0] + m[o*3+1]*y01[1] + m[o*3+2]*y01[2];
        float o10 = m[o*3+0]*y10[0] + m[o*3+1]*y10[1] + m[o*3+2]*y10[2];
        float o11 = m[o*3+0]*y11[0] + m[o*3+1]*y11[1] + m[o*3+2]*y11[2];
        size_t ob = ((size_t)(b * 3 + o) * HO + 2 * h) * WO + 2 * w;
        out[ob]          = o00;
        out[ob + 1]      = o01;
        out[ob + WO]     = o10;
        out[ob + WO + 1] = o11;
    }
}

// ---------------------------------------------------------------------------
// Host side
// ---------------------------------------------------------------------------
static inline int ceil_div(int a, int b) { return (a + b - 1) / b; }

extern "C" void kernel_launch(void* const* d_in, const int* in_sizes, int n_in,
                              void* d_out, int out_size) {
    (void)in_sizes; (void)n_in; (void)out_size;
    const float* x        = (const float*)d_in[0];
    const float* conv1_w  = (const float*)d_in[1];
    const float* conv1_b  = (const float*)d_in[2];
    const float* conv2_w  = (const float*)d_in[3];
    const float* conv2_b  = (const float*)d_in[4];
    const float* conv3_w  = (const float*)d_in[5];
    const float* conv3_b  = (const float*)d_in[6];
    const float* conv4_w  = (const float*)d_in[7];
    const float* conv4_b  = (const float*)d_in[8];
    const float* convd4_w = (const float*)d_in[9];
    const float* convd4_b = (const float*)d_in[10];
    const float* convd3_w = (const float*)d_in[11];
    const float* convd3_b = (const float*)d_in[12];
    const float* convd2_w = (const float*)d_in[13];
    const float* convd2_b = (const float*)d_in[14];
    const float* convd1_w = (const float*)d_in[15];
    const float* convd1_b = (const float*)d_in[16];
    const float* cfin_w   = (const float*)d_in[17];
    float* out = (float*)d_out;

    static float *p_w1=nullptr,*p_c1,*p_w2,*p_c2,*p_w3,*p_c3,*p_w4,*p_c4,*p_c5,
                 *p_ic4,*p_iw4,*p_ic3,*p_iw3,*p_ic2,*p_iw2,*p_ic1,*p_iw1,*p_part;
    if (!p_w1) {
        cudaGetSymbolAddress((void**)&p_w1,  g_w1);
        cudaGetSymbolAddress((void**)&p_c1,  g_c1);
        cudaGetSymbolAddress((void**)&p_w2,  g_w2);
        cudaGetSymbolAddress((void**)&p_c2,  g_c2);
        cudaGetSymbolAddress((void**)&p_w3,  g_w3);
        cudaGetSymbolAddress((void**)&p_c3,  g_c3);
        cudaGetSymbolAddress((void**)&p_w4,  g_w4);
        cudaGetSymbolAddress((void**)&p_c4,  g_c4);
        cudaGetSymbolAddress((void**)&p_c5,  g_c5);
        cudaGetSymbolAddress((void**)&p_ic4, g_ic4);
        cudaGetSymbolAddress((void**)&p_iw4, g_iw4);
        cudaGetSymbolAddress((void**)&p_ic3, g_ic3);
        cudaGetSymbolAddress((void**)&p_iw3, g_iw3);
        cudaGetSymbolAddress((void**)&p_ic2, g_ic2);
        cudaGetSymbolAddress((void**)&p_iw2, g_iw2);
        cudaGetSymbolAddress((void**)&p_ic1, g_ic1);
        cudaGetSymbolAddress((void**)&p_iw1, g_iw1);
        cudaGetSymbolAddress((void**)&p_part, g_part);
    }

    // w1 = wt(x)
    wt_k<<<ceil_div(4*3*128*128, 256), 256>>>(x, p_w1, 4, 3, 256, 256);

    // conv1: 12->16 @128². NP=2 (OCBLK=8), S=4 (ics=3). grid (256,2,4) x128
    convpart_k<128,128,64,2,2,3><<<dim3(256, 2, 4), 128>>>(
        p_w1, conv1_w, p_part, 12, 16, 3);
    combine4wt_k<<<ceil_div(1048576/4, 256), 256>>>(
        p_part, conv1_b, p_c1, p_w2, 16, 128, 128, 1048576);

    // conv2: 64->64 @64². S=4 (ics=16). grid (64,8,4) x128
    convpart_k<64,64,64,2,2,16><<<dim3(64, 8, 4), 128>>>(
        p_w2, conv2_w, p_part, 64, 64, 16);
    combine4wt_k<<<ceil_div(1048576/4, 256), 256>>>(
        p_part, conv2_b, p_c2, p_w3, 64, 64, 64, 1048576);

    // conv3: 256->256 @32². S=4 (ics=64). grid (16,32,4) x128
    convpart_k<32,32,64,2,2,16><<<dim3(16, 32, 4), 128>>>(
        p_w3, conv3_w, p_part, 256, 256, 64);
    combine4wt_k<<<ceil_div(1048576/4, 256), 256>>>(
        p_part, conv3_b, p_c3, p_w4, 256, 32, 32, 1048576);

    // bottleneck: three conv4 1024->1024 @16². S=4 (ics=256). grid (4,128,4)
    convpart_k<16,16,64,2,2,16><<<dim3(4, 128, 4), 128>>>(
        p_w4, conv4_w, p_part, 1024, 1024, 256);
    combine4_k<true,false><<<ceil_div(1048576/2, 256), 256>>>(
        p_part, conv4_b, nullptr, p_c4, 1024, 16*16, 1048576);
    convpart_k<16,16,64,2,2,16><<<dim3(4, 128, 4), 128>>>(
        p_c4, conv4_w, p_part, 1024, 1024, 256);
    combine4_k<true,false><<<ceil_div(1048576/2, 256), 256>>>(
        p_part, conv4_b, nullptr, p_c5, 1024, 16*16, 1048576);
    convpart_k<16,16,64,2,2,16><<<dim3(4, 128, 4), 128>>>(
        p_c5, conv4_w, p_part, 1024, 1024, 256);
    combine4_k<true,true><<<ceil_div(1048576/2, 256), 256>>>(
        p_part, conv4_b, p_w4, p_ic4, 1024, 16*16, 1048576);

    // decoder — fused iwt + skip concat
    iwtcat_k<<<ceil_div(4*256*16*16 + 4*256*2*16*16*2, 256), 256>>>(
        p_ic4, p_c3, p_iw4, 4, 1024, 16, 16, 512);

    // convd4: 512->256 @32². S=4 (ics=128). grid (16,32,4)
    convpart_k<32,32,64,2,2,16><<<dim3(16, 32, 4), 128>>>(
        p_iw4, convd4_w, p_part, 512, 256, 128);
    combine4_k<true,false><<<ceil_div(1048576/2, 256), 256>>>(
        p_part, convd4_b, nullptr, p_ic3, 256, 32*32, 1048576);

    iwtcat_k<<<ceil_div(4*64*32*32 + 4*64*2*32*32*2, 256), 256>>>(
        p_ic3, p_c2, p_iw3, 4, 256, 32, 32, 128);

    // convd3: 128->64 @64². S=4 (ics=32). grid (64,8,4)
    convpart_k<64,64,64,2,2,16><<<dim3(64, 8, 4), 128>>>(
        p_iw3, convd3_w, p_part, 128, 64, 32);
    combine4_k<true,false><<<ceil_div(1048576/2, 256), 256>>>(
        p_part, convd3_b, nullptr, p_ic2, 64, 64*64, 1048576);

    iwtcat_k<<<ceil_div(4*16*64*64 + 4*16*2*64*64*2, 256), 256>>>(
        p_ic2, p_c1, p_iw2, 4, 64, 64, 64, 32);

    // convd2: 32->16 @128². S=4 (ics=8). grid (256,2,4)
    convpart_k<128,128,64,2,2,8><<<dim3(256, 2, 4), 128>>>(
        p_iw2, convd2_w, p_part, 32, 16, 8);
    combine4_k<true,false><<<ceil_div(1048576/2, 256), 256>>>(
        p_part, convd2_b, nullptr, p_ic1, 16, 128*128, 1048576);

    // convd1: 16->12 @128². NP=3 (OCBLK=12), S=4 (ics=4). grid (256,1,4)
    convpart_k<128,128,64,2,3,4><<<dim3(256, 1, 4), 128>>>(
        p_ic1, convd1_w, p_part, 16, 12, 4);
    combine4_k<true,false><<<ceil_div(786432/2, 256), 256>>>(
        p_part, convd1_b, nullptr, p_iw1, 12, 128*128, 786432);

    // fused final iwt + 1x1
    final_k<<<ceil_div(4*128*128, 256), 256>>>(p_iw1, cfin_w, out, 4);
}

// round 12
// speedup vs baseline: 1.1212x; 1.1212x over previous
#include <cuda_runtime.h>
#include <cstdint>

typedef unsigned long long ull;

// ---------------------------------------------------------------------------
// Scratch buffers (device globals; no allocation allowed)
// ---------------------------------------------------------------------------
__device__ float g_w1 [786432];    // [4,12,128,128]
__device__ float g_c1 [1048576];   // [4,16,128,128]
__device__ float g_w2 [1048576];   // [4,64,64,64]
__device__ float g_c2 [1048576];   // [4,64,64,64]
__device__ float g_w3 [1048576];   // [4,256,32,32]
__device__ float g_c3 [1048576];   // [4,256,32,32]
__device__ float g_w4 [1048576];   // [4,1024,16,16]
__device__ float g_c4 [1048576];
__device__ float g_c5 [1048576];
__device__ float g_ic4[1048576];
__device__ float g_iw4[2097152];   // [4,512,32,32]
__device__ float g_ic3[1048576];   // [4,256,32,32]
__device__ float g_iw3[2097152];   // [4,128,64,64]
__device__ float g_ic2[1048576];   // [4,64,64,64]
__device__ float g_iw2[2097152];   // [4,32,128,128]
__device__ float g_ic1[1048576];   // [4,16,128,128]
__device__ float g_iw1[786432];    // [4,12,128,128]
__device__ float g_part[4194304];  // 4 x 1M partial-sum buffers

// ---------------------------------------------------------------------------
// f32x2 packed helpers (Blackwell FFMA2)
// ---------------------------------------------------------------------------
__device__ __forceinline__ ull pk(float x, float y) {
    ull r;
    asm("mov.b64 %0, {%1, %2};" : "=l"(r) : "f"(x), "f"(y));
    return r;
}
__device__ __forceinline__ void upk(float& x, float& y, ull v) {
    asm("mov.b64 {%0, %1}, %2;" : "=f"(x), "=f"(y) : "l"(v));
}
__device__ __forceinline__ void fma2(ull& d, ull a, ull b) {
    asm("fma.rn.f32x2 %0, %1, %2, %0;" : "+l"(d) : "l"(a), "l"(b));
}

// ---------------------------------------------------------------------------
// Haar DWT (standalone — only for the network input x)
// ---------------------------------------------------------------------------
__global__ void wt_k(const float* __restrict__ in, float* __restrict__ out,
                     int B, int C, int H, int W) {
    int Ho = H >> 1, Wo = W >> 1;
    int total = B * C * Ho * Wo;
    int i = blockIdx.x * blockDim.x + threadIdx.x;
    if (i >= total) return;
    int w = i % Wo;
    int h = (i / Wo) % Ho;
    int c = (i / (Wo * Ho)) % C;
    int b = i / (Wo * Ho * C);
    const float* p = in + ((size_t)(b * C + c) * H + 2 * h) * W + 2 * w;
    float a  = p[0], bb = p[1], cc = p[W], d = p[W + 1];
    float ll = 0.25f * (a + bb + cc + d);
    float hl = 0.5f  * (a + bb - cc - d);
    float lh = 0.5f  * (a - bb + cc - d);
    float hh = 0.5f  * (a - bb - cc + d);
    size_t ob = ((size_t)(b * 4 * C + 4 * c) * Ho + h) * Wo + w;
    size_t cs = (size_t)Ho * Wo;
    out[ob]          = ll;
    out[ob + cs]     = (hl + 1.f) * 0.5f;
    out[ob + 2 * cs] = (lh + 1.f) * 0.5f;
    out[ob + 3 * cs] = (hh + 1.f) * 0.5f;
}

// ---------------------------------------------------------------------------
// Fused IWT + skip-concat:  out[:, :Csrc] = skip;  out[:, Csrc:] = iwt(iwin)
// ---------------------------------------------------------------------------
__global__ void iwtcat_k(const float* __restrict__ iwin, const float* __restrict__ skip,
                         float* __restrict__ out, int B, int C4, int H, int W, int Ctot) {
    int C = C4 >> 2;
    int Csrc = Ctot - C;
    int HWo = 4 * H * W;
    int Niwt = B * C * H * W;
    int npc = HWo / 2;
    int Ncopy2 = B * Csrc * npc;
    int i = blockIdx.x * blockDim.x + threadIdx.x;
    if (i < Niwt) {
        int w = i % W;
        int h = (i / W) % H;
        int c = (i / (W * H)) % C;
        int b = i / (W * H * C);
        size_t ib = ((size_t)(b * C4 + 4 * c) * H + h) * W + w;
        size_t cs = (size_t)H * W;
        float v0 = iwin[ib];
        float v1 = 2.f * iwin[ib + cs]     - 1.f;
        float v2 = 2.f * iwin[ib + 2 * cs] - 1.f;
        float v3 = 2.f * iwin[ib + 3 * cs] - 1.f;
        float x00 = v0 + 0.5f * ( v1 + v2 + v3);
        float x01 = v0 + 0.5f * ( v1 - v2 - v3);
        float x10 = v0 + 0.5f * (-v1 + v2 - v3);
        float x11 = v0 + 0.5f * (-v1 - v2 + v3);
        int W2 = 2 * W;
        size_t ob = ((size_t)(b * Ctot + Csrc + c) * 2 * H + 2 * h) * W2 + 2 * w;
        out[ob]          = x00;
        out[ob + 1]      = x01;
        out[ob + W2]     = x10;
        out[ob + W2 + 1] = x11;
    } else {
        int j = i - Niwt;
        if (j >= Ncopy2) return;
        int pos = j % npc;
        int c   = (j / npc) % Csrc;
        int b   = j / (npc * Csrc);
        *(float2*)&out[((size_t)(b * Ctot) + c) * HWo + 2 * pos] =
            *(const float2*)&skip[((size_t)(b * Csrc) + c) * HWo + 2 * pos];
    }
}

// ---------------------------------------------------------------------------
// Partial direct 3x3 conv, pad=1 — oc-pair lane packing, 2x2 px per thread.
// NP oc-pairs per thread. Single-buffered input loads (TLP hides latency).
// blockIdx.z selects IC split; raw partials out. LDS.128 weight reads.
// ---------------------------------------------------------------------------
template <int H, int W, int TPX, int TOC, int NP, int ICCHUNK>
__global__ void __launch_bounds__(TPX * TOC, 6)
convpart_k(const float* __restrict__ in, const float* __restrict__ wgt,
           float* __restrict__ part, int IC, int OC, int ics) {
    constexpr int NT    = TPX * TOC;
    constexpr int OCBLK = TOC * 2 * NP;
    constexpr int PAIRS = OCBLK / 2;
    constexpr int WN    = OCBLK * ICCHUNK * 9;
    constexpr int DN    = ICCHUNK * 9 * PAIRS;
    constexpr int TILESIMG = (H / 2) * (W / 2);

    __shared__ __align__(16) float  s_raw[2][WN];
    __shared__ __align__(16) float2 s_dup[DN];

    const int tid = threadIdx.x;
    const int tpx = tid % TPX;
    const int toc = tid / TPX;
    const int g   = blockIdx.x * TPX + tpx;
    const int img = g / TILESIMG;
    const int rem = g % TILESIMG;
    const int h0  = (rem / (W / 2)) * 2;
    const int w0  = (rem % (W / 2)) * 2;
    const int oc0 = blockIdx.y * OCBLK;
    const int z   = blockIdx.z;
    const int ic0 = z * ics;
    const int pairbase = toc * NP;

    const size_t HW = (size_t)H * W;
    const bool vr0 = (h0 > 0);
    const bool vr3 = (h0 + 2 < H);
    const bool lok = (w0 > 0);
    const bool rok = (w0 + 2 < W);

    ull acc[NP][2][2];
#pragma unroll
    for (int np = 0; np < NP; np++)
#pragma unroll
        for (int r = 0; r < 2; r++)
#pragma unroll
            for (int c = 0; c < 2; c++) acc[np][r][c] = pk(0.f, 0.f);

    const float* p0 = in + ((size_t)img * IC + ic0) * HW + (size_t)(h0 - 1) * W + (w0 - 1);
    const int nch = ics / ICCHUNK;

    // prologue: prefetch weight chunk 0 of this split
    for (int i = tid; i < WN; i += NT) {
        int o = i / (ICCHUNK * 9);
        int r = i - o * (ICCHUNK * 9);
        const float* src = wgt + ((size_t)(oc0 + o) * IC + ic0) * 9 + r;
        uint32_t dst = (uint32_t)__cvta_generic_to_shared(&s_raw[0][i]);
        asm volatile("cp.async.ca.shared.global [%0], [%1], 4;" :: "r"(dst), "l"(src));
    }
    asm volatile("cp.async.commit_group;" ::: "memory");

    for (int ch = 0; ch < nch; ch++) {
        asm volatile("cp.async.wait_group 0;" ::: "memory");
        __syncthreads();
        // pack weights into oc-pair float2
        for (int i = tid; i < DN; i += NT) {
            int pr = i % PAIRS;
            int t  = i / PAIRS;
            s_dup[i] = make_float2(s_raw[ch & 1][(2 * pr) * (ICCHUNK * 9) + t],
                                   s_raw[ch & 1][(2 * pr + 1) * (ICCHUNK * 9) + t]);
        }
        if (ch + 1 < nch) {
            const int icn = ic0 + (ch + 1) * ICCHUNK;
            for (int i = tid; i < WN; i += NT) {
                int o = i / (ICCHUNK * 9);
                int r = i - o * (ICCHUNK * 9);
                const float* src = wgt + ((size_t)(oc0 + o) * IC + icn) * 9 + r;
                uint32_t dst = (uint32_t)__cvta_generic_to_shared(&s_raw[(ch + 1) & 1][i]);
                asm volatile("cp.async.ca.shared.global [%0], [%1], 4;" :: "r"(dst), "l"(src));
            }
        }
        asm volatile("cp.async.commit_group;" ::: "memory");
        __syncthreads();

        const float* pb = p0 + (size_t)(ch * ICCHUNK) * HW;
#pragma unroll 2
        for (int kk = 0; kk < ICCHUNK; kk++) {
            const float* pc = pb + (size_t)kk * HW;
            ull bp[4][4];
#pragma unroll
            for (int ri = 0; ri < 4; ri++) {
                bool vr = (ri == 0) ? vr0 : (ri == 3) ? vr3 : true;
                const float* q = pc + ri * W;
                float2 m = make_float2(0.f, 0.f);
                float l = 0.f, r = 0.f;
                if (vr) {
                    m = *(const float2*)(q + 1);
                    if (lok) l = q[0];
                    if (rok) r = q[3];
                }
                bp[ri][0] = pk(l, l);
                bp[ri][1] = pk(m.x, m.x);
                bp[ri][2] = pk(m.y, m.y);
                bp[ri][3] = pk(r, r);
            }
            const float2* wrow = s_dup + (size_t)kk * 9 * PAIRS + pairbase;
#pragma unroll
            for (int ki = 0; ki < 3; ki++)
#pragma unroll
                for (int kj = 0; kj < 3; kj++) {
                    const int t = ki * 3 + kj;
                    ull wv[NP];
                    if constexpr ((NP % 2) == 0) {
#pragma unroll
                        for (int q2 = 0; q2 < NP / 2; q2++) {
                            ulonglong2 u = *(const ulonglong2*)&wrow[t * PAIRS + 2 * q2];
                            wv[2 * q2]     = u.x;
                            wv[2 * q2 + 1] = u.y;
                        }
                    } else {
#pragma unroll
                        for (int np = 0; np < NP; np++)
                            wv[np] = *(const ull*)&wrow[t * PAIRS + np];
                    }
#pragma unroll
                    for (int np = 0; np < NP; np++) {
                        fma2(acc[np][0][0], bp[ki][kj],         wv[np]);
                        fma2(acc[np][0][1], bp[ki][kj + 1],     wv[np]);
                        fma2(acc[np][1][0], bp[ki + 1][kj],     wv[np]);
                        fma2(acc[np][1][1], bp[ki + 1][kj + 1], wv[np]);
                    }
                }
        }
    }

    // ---- store raw partials ----
    float* pout = part + (size_t)z * 4 * OC * HW;
#pragma unroll
    for (int np = 0; np < NP; np++) {
        float a00, b00, a01, b01, a10, b10, a11, b11;
        upk(a00, b00, acc[np][0][0]); upk(a01, b01, acc[np][0][1]);
        upk(a10, b10, acc[np][1][0]); upk(a11, b11, acc[np][1][1]);
        const int ocA = oc0 + 2 * (pairbase + np);
        size_t baseA = ((size_t)(img * OC + ocA) * H + h0) * W + w0;
        size_t baseB = baseA + HW;
        *(float2*)&pout[baseA]     = make_float2(a00, a01);
        *(float2*)&pout[baseA + W] = make_float2(a10, a11);
        *(float2*)&pout[baseB]     = make_float2(b00, b01);
        *(float2*)&pout[baseB + W] = make_float2(b10, b11);
    }
}

// ---------------------------------------------------------------------------
// Combine four partial buffers: out = act(p0+p1+p2+p3 + bias (+skip))
// ---------------------------------------------------------------------------
template <bool RELU, bool ADD>
__global__ void combine4_k(const float* __restrict__ part, const float* __restrict__ bias,
                           const float* __restrict__ addsrc, float* __restrict__ out,
                           int OC, int HW, int total) {
    int i = (blockIdx.x * blockDim.x + threadIdx.x) * 2;
    if (i >= total) return;
    int c = (i / HW) % OC;
    float2 p0 = *(const float2*)&part[i];
    float2 p1 = *(const float2*)&part[total + i];
    float2 p2 = *(const float2*)&part[2 * (size_t)total + i];
    float2 p3 = *(const float2*)&part[3 * (size_t)total + i];
    float bv = bias[c];
    float v0 = (p0.x + p1.x) + (p2.x + p3.x) + bv;
    float v1 = (p0.y + p1.y) + (p2.y + p3.y) + bv;
    if (ADD) {
        float2 s = *(const float2*)&addsrc[i];
        v0 += s.x; v1 += s.y;
    }
    if (RELU) {
        v0 = (v0 >= 0.f) ? v0 : 0.2f * v0;
        v1 = (v1 >= 0.f) ? v1 : 0.2f * v1;
    }
    *(float2*)&out[i] = make_float2(v0, v1);
}

// ---------------------------------------------------------------------------
// Combine four partials + lrelu + fused Haar DWT of the result.
// ---------------------------------------------------------------------------
__global__ void combine4wt_k(const float* __restrict__ part, const float* __restrict__ bias,
                             float* __restrict__ out, float* __restrict__ wtout,
                             int OC, int H, int W, int total) {
    int HW = H * W;
    int nblk = total / 4;
    int i = blockIdx.x * blockDim.x + threadIdx.x;
    if (i >= nblk) return;
    int Wh = W / 2;
    int w2 = i % Wh;
    int h2 = (i / Wh) % (H / 2);
    int bc = i / (HW / 4);
    size_t base = (size_t)bc * HW + (size_t)(2 * h2) * W + 2 * w2;
    float bv = bias[bc % OC];
    float v00 = bv, v01 = bv, v10 = bv, v11 = bv;
#pragma unroll
    for (int z = 0; z < 4; z++) {
        const float* p = part + (size_t)z * total;
        float2 a = *(const float2*)&p[base];
        float2 b = *(const float2*)&p[base + W];
        v00 += a.x; v01 += a.y; v10 += b.x; v11 += b.y;
    }
    v00 = (v00 >= 0.f) ? v00 : 0.2f * v00;
    v01 = (v01 >= 0.f) ? v01 : 0.2f * v01;
    v10 = (v10 >= 0.f) ? v10 : 0.2f * v10;
    v11 = (v11 >= 0.f) ? v11 : 0.2f * v11;
    *(float2*)&out[base]     = make_float2(v00, v01);
    *(float2*)&out[base + W] = make_float2(v10, v11);

    float ll = 0.25f * (v00 + v01 + v10 + v11);
    float hl = 0.5f  * (v00 + v01 - v10 - v11);
    float lh = 0.5f  * (v00 - v01 + v10 - v11);
    float hh = 0.5f  * (v00 - v01 - v10 + v11);
    hl = (hl + 1.f) * 0.5f; lh = (lh + 1.f) * 0.5f; hh = (hh + 1.f) * 0.5f;
    int c = bc % OC, b_ = bc / OC;
    size_t cs = (size_t)HW / 4;
    size_t ob = ((size_t)(b_ * 4 * OC + 4 * c)) * cs + (size_t)h2 * Wh + w2;
    wtout[ob]          = ll;
    wtout[ob + cs]     = hl;
    wtout[ob + 2 * cs] = lh;
    wtout[ob + 3 * cs] = hh;
}

// ---------------------------------------------------------------------------
// Final: y = iwt(iw1[4,12,128,128]); out = 1x1 conv cfin @ y -> [4,3,256,256]
// ---------------------------------------------------------------------------
__global__ void final_k(const float* __restrict__ in, const float* __restrict__ cfin,
                        float* __restrict__ out, int B) {
    const int H = 128, W = 128;
    int total = B * H * W;
    int i = blockIdx.x * blockDim.x + threadIdx.x;
    if (i >= total) return;
    int w = i % W;
    int h = (i / W) % H;
    int b = i / (W * H);

    float y00[3], y01[3], y10[3], y11[3];
#pragma unroll
    for (int c = 0; c < 3; c++) {
        size_t ib = ((size_t)(b * 12 + 4 * c) * H + h) * W + w;
        size_t cs = (size_t)H * W;
        float v0 = in[ib];
        float v1 = 2.f * in[ib + cs]     - 1.f;
        float v2 = 2.f * in[ib + 2 * cs] - 1.f;
        float v3 = 2.f * in[ib + 3 * cs] - 1.f;
        y00[c] = v0 + 0.5f * ( v1 + v2 + v3);
        y01[c] = v0 + 0.5f * ( v1 - v2 - v3);
        y10[c] = v0 + 0.5f * (-v1 + v2 - v3);
        y11[c] = v0 + 0.5f * (-v1 - v2 + v3);
    }
    float m[9];
#pragma unroll
    for (int j = 0; j < 9; j++) m[j] = cfin[j];

    const int HO = 256, WO = 256;
#pragma unroll
    for (int o = 0; o < 3; o++) {
        float o00 = m[o*3+0]*y00[0] + m[o*3+1]*y00[1] + m[o*3+2]*y00[2];
        float o01 = m[o*3+0]*y01[0] + m[o*3+1]*y01[1] + m[o*3+2]*y01[2];
        float o10 = m[o*3+0]*y10[0] + m[o*3+1]*y10[1] + m[o*3+2]*y10[2];
        float o11 = m[o*3+0]*y11[0] + m[o*3+1]*y11[1] + m[o*3+2]*y11[2];
        size_t ob = ((size_t)(b * 3 + o) * HO + 2 * h) * WO + 2 * w;
        out[ob]          = o00;
        out[ob + 1]      = o01;
        out[ob + WO]     = o10;
        out[ob + WO + 1] = o11;
    }
}

// ---------------------------------------------------------------------------
// Host side
// ---------------------------------------------------------------------------
static inline int ceil_div(int a, int b) { return (a + b - 1) / b; }

extern "C" void kernel_launch(void* const* d_in, const int* in_sizes, int n_in,
                              void* d_out, int out_size) {
    (void)in_sizes; (void)n_in; (void)out_size;
    const float* x        = (const float*)d_in[0];
    const float* conv1_w  = (const float*)d_in[1];
    const float* conv1_b  = (const float*)d_in[2];
    const float* conv2_w  = (const float*)d_in[3];
    const float* conv2_b  = (const float*)d_in[4];
    const float* conv3_w  = (const float*)d_in[5];
    const float* conv3_b  = (const float*)d_in[6];
    const float* conv4_w  = (const float*)d_in[7];
    const float* conv4_b  = (const float*)d_in[8];
    const float* convd4_w = (const float*)d_in[9];
    const float* convd4_b = (const float*)d_in[10];
    const float* convd3_w = (const float*)d_in[11];
    const float* convd3_b = (const float*)d_in[12];
    const float* convd2_w = (const float*)d_in[13];
    const float* convd2_b = (const float*)d_in[14];
    const float* convd1_w = (const float*)d_in[15];
    const float* convd1_b = (const float*)d_in[16];
    const float* cfin_w   = (const float*)d_in[17];
    float* out = (float*)d_out;

    static float *p_w1=nullptr,*p_c1,*p_w2,*p_c2,*p_w3,*p_c3,*p_w4,*p_c4,*p_c5,
                 *p_ic4,*p_iw4,*p_ic3,*p_iw3,*p_ic2,*p_iw2,*p_ic1,*p_iw1,*p_part;
    if (!p_w1) {
        cudaGetSymbolAddress((void**)&p_w1,  g_w1);
        cudaGetSymbolAddress((void**)&p_c1,  g_c1);
        cudaGetSymbolAddress((void**)&p_w2,  g_w2);
        cudaGetSymbolAddress((void**)&p_c2,  g_c2);
        cudaGetSymbolAddress((void**)&p_w3,  g_w3);
        cudaGetSymbolAddress((void**)&p_c3,  g_c3);
        cudaGetSymbolAddress((void**)&p_w4,  g_w4);
        cudaGetSymbolAddress((void**)&p_c4,  g_c4);
        cudaGetSymbolAddress((void**)&p_c5,  g_c5);
        cudaGetSymbolAddress((void**)&p_ic4, g_ic4);
        cudaGetSymbolAddress((void**)&p_iw4, g_iw4);
        cudaGetSymbolAddress((void**)&p_ic3, g_ic3);
        cudaGetSymbolAddress((void**)&p_iw3, g_iw3);
        cudaGetSymbolAddress((void**)&p_ic2, g_ic2);
        cudaGetSymbolAddress((void**)&p_iw2, g_iw2);
        cudaGetSymbolAddress((void**)&p_ic1, g_ic1);
        cudaGetSymbolAddress((void**)&p_iw1, g_iw1);
        cudaGetSymbolAddress((void**)&p_part, g_part);
    }

    // w1 = wt(x)
    wt_k<<<ceil_div(4*3*128*128, 256), 256>>>(x, p_w1, 4, 3, 256, 256);

    // conv1: 12->16 @128². NP=4 (OCBLK=16), S=4 (ics=3). grid (256,1,4) x128
    convpart_k<128,128,64,2,4,3><<<dim3(256, 1, 4), 128>>>(
        p_w1, conv1_w, p_part, 12, 16, 3);
    combine4wt_k<<<ceil_div(1048576/4, 256), 256>>>(
        p_part, conv1_b, p_c1, p_w2, 16, 128, 128, 1048576);

    // conv2: 64->64 @64². NP=4, S=4 (ics=16). grid (64,4,4) x128
    convpart_k<64,64,64,2,4,16><<<dim3(64, 4, 4), 128>>>(
        p_w2, conv2_w, p_part, 64, 64, 16);
    combine4wt_k<<<ceil_div(1048576/4, 256), 256>>>(
        p_part, conv2_b, p_c2, p_w3, 64, 64, 64, 1048576);

    // conv3: 256->256 @32². NP=4, S=4 (ics=64). grid (16,16,4) x128
    convpart_k<32,32,64,2,4,16><<<dim3(16, 16, 4), 128>>>(
        p_w3, conv3_w, p_part, 256, 256, 64);
    combine4wt_k<<<ceil_div(1048576/4, 256), 256>>>(
        p_part, conv3_b, p_c3, p_w4, 256, 32, 32, 1048576);

    // bottleneck: three conv4 1024->1024 @16². NP=4, S=4 (ics=256). grid (4,64,4)
    convpart_k<16,16,64,2,4,16><<<dim3(4, 64, 4), 128>>>(
        p_w4, conv4_w, p_part, 1024, 1024, 256);
    combine4_k<true,false><<<ceil_div(1048576/2, 256), 256>>>(
        p_part, conv4_b, nullptr, p_c4, 1024, 16*16, 1048576);
    convpart_k<16,16,64,2,4,16><<<dim3(4, 64, 4), 128>>>(
        p_c4, conv4_w, p_part, 1024, 1024, 256);
    combine4_k<true,false><<<ceil_div(1048576/2, 256), 256>>>(
        p_part, conv4_b, nullptr, p_c5, 1024, 16*16, 1048576);
    convpart_k<16,16,64,2,4,16><<<dim3(4, 64, 4), 128>>>(
        p_c5, conv4_w, p_part, 1024, 1024, 256);
    combine4_k<true,true><<<ceil_div(1048576/2, 256), 256>>>(
        p_part, conv4_b, p_w4, p_ic4, 1024, 16*16, 1048576);

    // decoder — fused iwt + skip concat
    iwtcat_k<<<ceil_div(4*256*16*16 + 4*256*2*16*16*2, 256), 256>>>(
        p_ic4, p_c3, p_iw4, 4, 1024, 16, 16, 512);

    // convd4: 512->256 @32². NP=4, S=4 (ics=128). grid (16,16,4)
    convpart_k<32,32,64,2,4,16><<<dim3(16, 16, 4), 128>>>(
        p_iw4, convd4_w, p_part, 512, 256, 128);
    combine4_k<true,false><<<ceil_div(1048576/2, 256), 256>>>(
        p_part, convd4_b, nullptr, p_ic3, 256, 32*32, 1048576);

    iwtcat_k<<<ceil_div(4*64*32*32 + 4*64*2*32*32*2, 256), 256>>>(
        p_ic3, p_c2, p_iw3, 4, 256, 32, 32, 128);

    // convd3: 128->64 @64². NP=4, S=4 (ics=32). grid (64,4,4)
    convpart_k<64,64,64,2,4,16><<<dim3(64, 4, 4), 128>>>(
        p_iw3, convd3_w, p_part, 128, 64, 32);
    combine4_k<true,false><<<ceil_div(1048576/2, 256), 256>>>(
        p_part, convd3_b, nullptr, p_ic2, 64, 64*64, 1048576);

    iwtcat_k<<<ceil_div(4*16*64*64 + 4*16*2*64*64*2, 256), 256>>>(
        p_ic2, p_c1, p_iw2, 4, 64, 64, 64, 32);

    // convd2: 32->16 @128². NP=4, S=4 (ics=8). grid (256,1,4)
    convpart_k<128,128,64,2,4,8><<<dim3(256, 1, 4), 128>>>(
        p_iw2, convd2_w, p_part, 32, 16, 8);
    combine4_k<true,false><<<ceil_div(1048576/2, 256), 256>>>(
        p_part, convd2_b, nullptr, p_ic1, 16, 128*128, 1048576);

    // convd1: 16->12 @128². NP=3 (OCBLK=12), S=4 (ics=4). grid (256,1,4)
    convpart_k<128,128,64,2,3,4><<<dim3(256, 1, 4), 128>>>(
        p_ic1, convd1_w, p_part, 16, 12, 4);
    combine4_k<true,false><<<ceil_div(786432/2, 256), 256>>>(
        p_part, convd1_b, nullptr, p_iw1, 12, 128*128, 786432);

    // fused final iwt + 1x1
    final_k<<<ceil_div(4*128*128, 256), 256>>>(p_iw1, cfin_w, out, 4);
}

// round 13
// speedup vs baseline: 1.2365x; 1.1028x over previous
#include <cuda_runtime.h>
#include <cstdint>

typedef unsigned long long ull;

// ---------------------------------------------------------------------------
// Scratch buffers (device globals; no allocation allowed)
// ---------------------------------------------------------------------------
__device__ float g_w1 [786432];    // [4,12,128,128]
__device__ float g_c1 [1048576];   // [4,16,128,128]
__device__ float g_w2 [1048576];   // [4,64,64,64]
__device__ float g_c2 [1048576];   // [4,64,64,64]
__device__ float g_w3 [1048576];   // [4,256,32,32]
__device__ float g_c3 [1048576];   // [4,256,32,32]
__device__ float g_w4 [1048576];   // [4,1024,16,16]
__device__ float g_c4 [1048576];
__device__ float g_c5 [1048576];
__device__ float g_ic4[1048576];
__device__ float g_iw4[2097152];   // [4,512,32,32]
__device__ float g_ic3[1048576];   // [4,256,32,32]
__device__ float g_iw3[2097152];   // [4,128,64,64]
__device__ float g_ic2[1048576];   // [4,64,64,64]
__device__ float g_iw2[2097152];   // [4,32,128,128]
__device__ float g_ic1[1048576];   // [4,16,128,128]
__device__ float g_iw1[786432];    // [4,12,128,128]
__device__ float g_part[4194304];  // 4 x 1M partial-sum buffers

// ---------------------------------------------------------------------------
// f32x2 packed helpers (Blackwell FFMA2)
// ---------------------------------------------------------------------------
__device__ __forceinline__ ull pk(float x, float y) {
    ull r;
    asm("mov.b64 %0, {%1, %2};" : "=l"(r) : "f"(x), "f"(y));
    return r;
}
__device__ __forceinline__ void upk(float& x, float& y, ull v) {
    asm("mov.b64 {%0, %1}, %2;" : "=f"(x), "=f"(y) : "l"(v));
}
__device__ __forceinline__ void fma2(ull& d, ull a, ull b) {
    asm("fma.rn.f32x2 %0, %1, %2, %0;" : "+l"(d) : "l"(a), "l"(b));
}

// ---------------------------------------------------------------------------
// Haar DWT (standalone — only for the network input x)
// ---------------------------------------------------------------------------
__global__ void wt_k(const float* __restrict__ in, float* __restrict__ out,
                     int B, int C, int H, int W) {
    int Ho = H >> 1, Wo = W >> 1;
    int total = B * C * Ho * Wo;
    int i = blockIdx.x * blockDim.x + threadIdx.x;
    if (i >= total) return;
    int w = i % Wo;
    int h = (i / Wo) % Ho;
    int c = (i / (Wo * Ho)) % C;
    int b = i / (Wo * Ho * C);
    const float* p = in + ((size_t)(b * C + c) * H + 2 * h) * W + 2 * w;
    float a  = p[0], bb = p[1], cc = p[W], d = p[W + 1];
    float ll = 0.25f * (a + bb + cc + d);
    float hl = 0.5f  * (a + bb - cc - d);
    float lh = 0.5f  * (a - bb + cc - d);
    float hh = 0.5f  * (a - bb - cc + d);
    size_t ob = ((size_t)(b * 4 * C + 4 * c) * Ho + h) * Wo + w;
    size_t cs = (size_t)Ho * Wo;
    out[ob]          = ll;
    out[ob + cs]     = (hl + 1.f) * 0.5f;
    out[ob + 2 * cs] = (lh + 1.f) * 0.5f;
    out[ob + 3 * cs] = (hh + 1.f) * 0.5f;
}

// ---------------------------------------------------------------------------
// Fused IWT + skip-concat:  out[:, :Csrc] = skip;  out[:, Csrc:] = iwt(iwin)
// ---------------------------------------------------------------------------
__global__ void iwtcat_k(const float* __restrict__ iwin, const float* __restrict__ skip,
                         float* __restrict__ out, int B, int C4, int H, int W, int Ctot) {
    int C = C4 >> 2;
    int Csrc = Ctot - C;
    int HWo = 4 * H * W;
    int Niwt = B * C * H * W;
    int npc = HWo / 2;
    int Ncopy2 = B * Csrc * npc;
    int i = blockIdx.x * blockDim.x + threadIdx.x;
    if (i < Niwt) {
        int w = i % W;
        int h = (i / W) % H;
        int c = (i / (W * H)) % C;
        int b = i / (W * H * C);
        size_t ib = ((size_t)(b * C4 + 4 * c) * H + h) * W + w;
        size_t cs = (size_t)H * W;
        float v0 = iwin[ib];
        float v1 = 2.f * iwin[ib + cs]     - 1.f;
        float v2 = 2.f * iwin[ib + 2 * cs] - 1.f;
        float v3 = 2.f * iwin[ib + 3 * cs] - 1.f;
        float x00 = v0 + 0.5f * ( v1 + v2 + v3);
        float x01 = v0 + 0.5f * ( v1 - v2 - v3);
        float x10 = v0 + 0.5f * (-v1 + v2 - v3);
        float x11 = v0 + 0.5f * (-v1 - v2 + v3);
        int W2 = 2 * W;
        size_t ob = ((size_t)(b * Ctot + Csrc + c) * 2 * H + 2 * h) * W2 + 2 * w;
        out[ob]          = x00;
        out[ob + 1]      = x01;
        out[ob + W2]     = x10;
        out[ob + W2 + 1] = x11;
    } else {
        int j = i - Niwt;
        if (j >= Ncopy2) return;
        int pos = j % npc;
        int c   = (j / npc) % Csrc;
        int b   = j / (npc * Csrc);
        *(float2*)&out[((size_t)(b * Ctot) + c) * HWo + 2 * pos] =
            *(const float2*)&skip[((size_t)(b * Csrc) + c) * HWo + 2 * pos];
    }
}

// ---------------------------------------------------------------------------
// Partial direct 3x3 conv, pad=1 — oc-pair lane packing, 2x2 px per thread.
// NP oc-pairs per thread, explicit per-thread input double-buffer (R10 core).
// 64-thread blocks (TOC=1) for high residency (10 blocks/SM).
// blockIdx.z selects IC split; raw partials out. LDS.128 weight reads.
// ---------------------------------------------------------------------------
template <int H, int W, int TPX, int TOC, int NP, int ICCHUNK>
__global__ void __launch_bounds__(TPX * TOC, 10)
convpart_k(const float* __restrict__ in, const float* __restrict__ wgt,
           float* __restrict__ part, int IC, int OC, int ics) {
    constexpr int NT    = TPX * TOC;
    constexpr int OCBLK = TOC * 2 * NP;
    constexpr int PAIRS = OCBLK / 2;
    constexpr int WN    = OCBLK * ICCHUNK * 9;
    constexpr int DN    = ICCHUNK * 9 * PAIRS;
    constexpr int TILESIMG = (H / 2) * (W / 2);

    __shared__ __align__(16) float  s_raw[2][WN];
    __shared__ __align__(16) float2 s_dup[DN];

    const int tid = threadIdx.x;
    const int tpx = tid % TPX;
    const int toc = tid / TPX;
    const int g   = blockIdx.x * TPX + tpx;
    const int img = g / TILESIMG;
    const int rem = g % TILESIMG;
    const int h0  = (rem / (W / 2)) * 2;
    const int w0  = (rem % (W / 2)) * 2;
    const int oc0 = blockIdx.y * OCBLK;
    const int z   = blockIdx.z;
    const int ic0 = z * ics;
    const int pairbase = toc * NP;

    const size_t HW = (size_t)H * W;
    const bool vr0 = (h0 > 0);
    const bool vr3 = (h0 + 2 < H);
    const bool lok = (w0 > 0);
    const bool rok = (w0 + 2 < W);

    ull acc[NP][2][2];
#pragma unroll
    for (int np = 0; np < NP; np++)
#pragma unroll
        for (int r = 0; r < 2; r++)
#pragma unroll
            for (int c = 0; c < 2; c++) acc[np][r][c] = pk(0.f, 0.f);

    const float* p0 = in + ((size_t)img * IC + ic0) * HW + (size_t)(h0 - 1) * W + (w0 - 1);
    const int nch = ics / ICCHUNK;

    // prologue: prefetch weight chunk 0 of this split
    for (int i = tid; i < WN; i += NT) {
        int o = i / (ICCHUNK * 9);
        int r = i - o * (ICCHUNK * 9);
        const float* src = wgt + ((size_t)(oc0 + o) * IC + ic0) * 9 + r;
        uint32_t dst = (uint32_t)__cvta_generic_to_shared(&s_raw[0][i]);
        asm volatile("cp.async.ca.shared.global [%0], [%1], 4;" :: "r"(dst), "l"(src));
    }
    asm volatile("cp.async.commit_group;" ::: "memory");

    float cl[2][4], cx[2][4], cy[2][4], cr[2][4];

    for (int ch = 0; ch < nch; ch++) {
        asm volatile("cp.async.wait_group 0;" ::: "memory");
        __syncthreads();
        // pack weights into oc-pair float2
        for (int i = tid; i < DN; i += NT) {
            int pr = i % PAIRS;
            int t  = i / PAIRS;
            s_dup[i] = make_float2(s_raw[ch & 1][(2 * pr) * (ICCHUNK * 9) + t],
                                   s_raw[ch & 1][(2 * pr + 1) * (ICCHUNK * 9) + t]);
        }
        if (ch + 1 < nch) {
            const int icn = ic0 + (ch + 1) * ICCHUNK;
            for (int i = tid; i < WN; i += NT) {
                int o = i / (ICCHUNK * 9);
                int r = i - o * (ICCHUNK * 9);
                const float* src = wgt + ((size_t)(oc0 + o) * IC + icn) * 9 + r;
                uint32_t dst = (uint32_t)__cvta_generic_to_shared(&s_raw[(ch + 1) & 1][i]);
                asm volatile("cp.async.ca.shared.global [%0], [%1], 4;" :: "r"(dst), "l"(src));
            }
        }
        asm volatile("cp.async.commit_group;" ::: "memory");
        __syncthreads();

        const float* pb = p0 + (size_t)(ch * ICCHUNK) * HW;
        // load ic 0 of chunk into buffer 0
#pragma unroll
        for (int ri = 0; ri < 4; ri++) {
            bool vr = (ri == 0) ? vr0 : (ri == 3) ? vr3 : true;
            const float* q = pb + ri * W;
            float2 m = make_float2(0.f, 0.f);
            float l = 0.f, r = 0.f;
            if (vr) {
                m = *(const float2*)(q + 1);
                if (lok) l = q[0];
                if (rok) r = q[3];
            }
            cl[0][ri] = l; cx[0][ri] = m.x; cy[0][ri] = m.y; cr[0][ri] = r;
        }

#pragma unroll 2
        for (int kk = 0; kk < ICCHUNK; kk++) {
            const int cb = kk & 1;
            // prefetch next ic
            if (kk + 1 < ICCHUNK) {
                const float* pn = pb + (size_t)(kk + 1) * HW;
#pragma unroll
                for (int ri = 0; ri < 4; ri++) {
                    bool vr = (ri == 0) ? vr0 : (ri == 3) ? vr3 : true;
                    const float* q = pn + ri * W;
                    float2 m = make_float2(0.f, 0.f);
                    float l = 0.f, r = 0.f;
                    if (vr) {
                        m = *(const float2*)(q + 1);
                        if (lok) l = q[0];
                        if (rok) r = q[3];
                    }
                    cl[cb ^ 1][ri] = l; cx[cb ^ 1][ri] = m.x;
                    cy[cb ^ 1][ri] = m.y; cr[cb ^ 1][ri] = r;
                }
            }
            // broadcast-pack current ic
            ull bp[4][4];
#pragma unroll
            for (int ri = 0; ri < 4; ri++) {
                bp[ri][0] = pk(cl[cb][ri], cl[cb][ri]);
                bp[ri][1] = pk(cx[cb][ri], cx[cb][ri]);
                bp[ri][2] = pk(cy[cb][ri], cy[cb][ri]);
                bp[ri][3] = pk(cr[cb][ri], cr[cb][ri]);
            }
            const float2* wrow = s_dup + (size_t)kk * 9 * PAIRS + pairbase;
#pragma unroll
            for (int ki = 0; ki < 3; ki++)
#pragma unroll
                for (int kj = 0; kj < 3; kj++) {
                    const int t = ki * 3 + kj;
                    ull wv[NP];
                    if constexpr ((NP % 2) == 0) {
#pragma unroll
                        for (int q2 = 0; q2 < NP / 2; q2++) {
                            ulonglong2 u = *(const ulonglong2*)&wrow[t * PAIRS + 2 * q2];
                            wv[2 * q2]     = u.x;
                            wv[2 * q2 + 1] = u.y;
                        }
                    } else {
#pragma unroll
                        for (int np = 0; np < NP; np++)
                            wv[np] = *(const ull*)&wrow[t * PAIRS + np];
                    }
#pragma unroll
                    for (int np = 0; np < NP; np++) {
                        fma2(acc[np][0][0], bp[ki][kj],         wv[np]);
                        fma2(acc[np][0][1], bp[ki][kj + 1],     wv[np]);
                        fma2(acc[np][1][0], bp[ki + 1][kj],     wv[np]);
                        fma2(acc[np][1][1], bp[ki + 1][kj + 1], wv[np]);
                    }
                }
        }
    }

    // ---- store raw partials ----
    float* pout = part + (size_t)z * 4 * OC * HW;
#pragma unroll
    for (int np = 0; np < NP; np++) {
        float a00, b00, a01, b01, a10, b10, a11, b11;
        upk(a00, b00, acc[np][0][0]); upk(a01, b01, acc[np][0][1]);
        upk(a10, b10, acc[np][1][0]); upk(a11, b11, acc[np][1][1]);
        const int ocA = oc0 + 2 * (pairbase + np);
        size_t baseA = ((size_t)(img * OC + ocA) * H + h0) * W + w0;
        size_t baseB = baseA + HW;
        *(float2*)&pout[baseA]     = make_float2(a00, a01);
        *(float2*)&pout[baseA + W] = make_float2(a10, a11);
        *(float2*)&pout[baseB]     = make_float2(b00, b01);
        *(float2*)&pout[baseB + W] = make_float2(b10, b11);
    }
}

// ---------------------------------------------------------------------------
// Combine four partial buffers: out = act(p0+p1+p2+p3 + bias (+skip))
// ---------------------------------------------------------------------------
template <bool RELU, bool ADD>
__global__ void combine4_k(const float* __restrict__ part, const float* __restrict__ bias,
                           const float* __restrict__ addsrc, float* __restrict__ out,
                           int OC, int HW, int total) {
    int i = (blockIdx.x * blockDim.x + threadIdx.x) * 2;
    if (i >= total) return;
    int c = (i / HW) % OC;
    float2 p0 = *(const float2*)&part[i];
    float2 p1 = *(const float2*)&part[total + i];
    float2 p2 = *(const float2*)&part[2 * (size_t)total + i];
    float2 p3 = *(const float2*)&part[3 * (size_t)total + i];
    float bv = bias[c];
    float v0 = (p0.x + p1.x) + (p2.x + p3.x) + bv;
    float v1 = (p0.y + p1.y) + (p2.y + p3.y) + bv;
    if (ADD) {
        float2 s = *(const float2*)&addsrc[i];
        v0 += s.x; v1 += s.y;
    }
    if (RELU) {
        v0 = (v0 >= 0.f) ? v0 : 0.2f * v0;
        v1 = (v1 >= 0.f) ? v1 : 0.2f * v1;
    }
    *(float2*)&out[i] = make_float2(v0, v1);
}

// ---------------------------------------------------------------------------
// Combine four partials + lrelu + fused Haar DWT of the result.
// ---------------------------------------------------------------------------
__global__ void combine4wt_k(const float* __restrict__ part, const float* __restrict__ bias,
                             float* __restrict__ out, float* __restrict__ wtout,
                             int OC, int H, int W, int total) {
    int HW = H * W;
    int nblk = total / 4;
    int i = blockIdx.x * blockDim.x + threadIdx.x;
    if (i >= nblk) return;
    int Wh = W / 2;
    int w2 = i % Wh;
    int h2 = (i / Wh) % (H / 2);
    int bc = i / (HW / 4);
    size_t base = (size_t)bc * HW + (size_t)(2 * h2) * W + 2 * w2;
    float bv = bias[bc % OC];
    float v00 = bv, v01 = bv, v10 = bv, v11 = bv;
#pragma unroll
    for (int z = 0; z < 4; z++) {
        const float* p = part + (size_t)z * total;
        float2 a = *(const float2*)&p[base];
        float2 b = *(const float2*)&p[base + W];
        v00 += a.x; v01 += a.y; v10 += b.x; v11 += b.y;
    }
    v00 = (v00 >= 0.f) ? v00 : 0.2f * v00;
    v01 = (v01 >= 0.f) ? v01 : 0.2f * v01;
    v10 = (v10 >= 0.f) ? v10 : 0.2f * v10;
    v11 = (v11 >= 0.f) ? v11 : 0.2f * v11;
    *(float2*)&out[base]     = make_float2(v00, v01);
    *(float2*)&out[base + W] = make_float2(v10, v11);

    float ll = 0.25f * (v00 + v01 + v10 + v11);
    float hl = 0.5f  * (v00 + v01 - v10 - v11);
    float lh = 0.5f  * (v00 - v01 + v10 - v11);
    float hh = 0.5f  * (v00 - v01 - v10 + v11);
    hl = (hl + 1.f) * 0.5f; lh = (lh + 1.f) * 0.5f; hh = (hh + 1.f) * 0.5f;
    int c = bc % OC, b_ = bc / OC;
    size_t cs = (size_t)HW / 4;
    size_t ob = ((size_t)(b_ * 4 * OC + 4 * c)) * cs + (size_t)h2 * Wh + w2;
    wtout[ob]          = ll;
    wtout[ob + cs]     = hl;
    wtout[ob + 2 * cs] = lh;
    wtout[ob + 3 * cs] = hh;
}

// ---------------------------------------------------------------------------
// Final: y = iwt(iw1[4,12,128,128]); out = 1x1 conv cfin @ y -> [4,3,256,256]
// ---------------------------------------------------------------------------
__global__ void final_k(const float* __restrict__ in, const float* __restrict__ cfin,
                        float* __restrict__ out, int B) {
    const int H = 128, W = 128;
    int total = B * H * W;
    int i = blockIdx.x * blockDim.x + threadIdx.x;
    if (i >= total) return;
    int w = i % W;
    int h = (i / W) % H;
    int b = i / (W * H);

    float y00[3], y01[3], y10[3], y11[3];
#pragma unroll
    for (int c = 0; c < 3; c++) {
        size_t ib = ((size_t)(b * 12 + 4 * c) * H + h) * W + w;
        size_t cs = (size_t)H * W;
        float v0 = in[ib];
        float v1 = 2.f * in[ib + cs]     - 1.f;
        float v2 = 2.f * in[ib + 2 * cs] - 1.f;
        float v3 = 2.f * in[ib + 3 * cs] - 1.f;
        y00[c] = v0 + 0.5f * ( v1 + v2 + v3);
        y01[c] = v0 + 0.5f * ( v1 - v2 - v3);
        y10[c] = v0 + 0.5f * (-v1 + v2 - v3);
        y11[c] = v0 + 0.5f * (-v1 - v2 + v3);
    }
    float m[9];
#pragma unroll
    for (int j = 0; j < 9; j++) m[j] = cfin[j];

    const int HO = 256, WO = 256;
#pragma unroll
    for (int o = 0; o < 3; o++) {
        float o00 = m[o*3+0]*y00[0] + m[o*3+1]*y00[1] + m[o*3+2]*y00[2];
        float o01 = m[o*3+0]*y01[0] + m[o*3+1]*y01[1] + m[o*3+2]*y01[2];
        float o10 = m[o*3+0]*y10[0] + m[o*3+1]*y10[1] + m[o*3+2]*y10[2];
        float o11 = m[o*3+0]*y11[0] + m[o*3+1]*y11[1] + m[o*3+2]*y11[2];
        size_t ob = ((size_t)(b * 3 + o) * HO + 2 * h) * WO + 2 * w;
        out[ob]          = o00;
        out[ob + 1]      = o01;
        out[ob + WO]     = o10;
        out[ob + WO + 1] = o11;
    }
}

// ---------------------------------------------------------------------------
// Host side
// ---------------------------------------------------------------------------
static inline int ceil_div(int a, int b) { return (a + b - 1) / b; }

extern "C" void kernel_launch(void* const* d_in, const int* in_sizes, int n_in,
                              void* d_out, int out_size) {
    (void)in_sizes; (void)n_in; (void)out_size;
    const float* x        = (const float*)d_in[0];
    const float* conv1_w  = (const float*)d_in[1];
    const float* conv1_b  = (const float*)d_in[2];
    const float* conv2_w  = (const float*)d_in[3];
    const float* conv2_b  = (const float*)d_in[4];
    const float* conv3_w  = (const float*)d_in[5];
    const float* conv3_b  = (const float*)d_in[6];
    const float* conv4_w  = (const float*)d_in[7];
    const float* conv4_b  = (const float*)d_in[8];
    const float* convd4_w = (const float*)d_in[9];
    const float* convd4_b = (const float*)d_in[10];
    const float* convd3_w = (const float*)d_in[11];
    const float* convd3_b = (const float*)d_in[12];
    const float* convd2_w = (const float*)d_in[13];
    const float* convd2_b = (const float*)d_in[14];
    const float* convd1_w = (const float*)d_in[15];
    const float* convd1_b = (const float*)d_in[16];
    const float* cfin_w   = (const float*)d_in[17];
    float* out = (float*)d_out;

    static float *p_w1=nullptr,*p_c1,*p_w2,*p_c2,*p_w3,*p_c3,*p_w4,*p_c4,*p_c5,
                 *p_ic4,*p_iw4,*p_ic3,*p_iw3,*p_ic2,*p_iw2,*p_ic1,*p_iw1,*p_part;
    if (!p_w1) {
        cudaGetSymbolAddress((void**)&p_w1,  g_w1);
        cudaGetSymbolAddress((void**)&p_c1,  g_c1);
        cudaGetSymbolAddress((void**)&p_w2,  g_w2);
        cudaGetSymbolAddress((void**)&p_c2,  g_c2);
        cudaGetSymbolAddress((void**)&p_w3,  g_w3);
        cudaGetSymbolAddress((void**)&p_c3,  g_c3);
        cudaGetSymbolAddress((void**)&p_w4,  g_w4);
        cudaGetSymbolAddress((void**)&p_c4,  g_c4);
        cudaGetSymbolAddress((void**)&p_c5,  g_c5);
        cudaGetSymbolAddress((void**)&p_ic4, g_ic4);
        cudaGetSymbolAddress((void**)&p_iw4, g_iw4);
        cudaGetSymbolAddress((void**)&p_ic3, g_ic3);
        cudaGetSymbolAddress((void**)&p_iw3, g_iw3);
        cudaGetSymbolAddress((void**)&p_ic2, g_ic2);
        cudaGetSymbolAddress((void**)&p_iw2, g_iw2);
        cudaGetSymbolAddress((void**)&p_ic1, g_ic1);
        cudaGetSymbolAddress((void**)&p_iw1, g_iw1);
        cudaGetSymbolAddress((void**)&p_part, g_part);
    }

    // w1 = wt(x)
    wt_k<<<ceil_div(4*3*128*128, 256), 256>>>(x, p_w1, 4, 3, 256, 256);

    // conv1: 12->16 @128². 64thr blocks, OCBLK=8, S=4. grid (256,2,4)=2048
    convpart_k<128,128,64,1,4,3><<<dim3(256, 2, 4), 64>>>(
        p_w1, conv1_w, p_part, 12, 16, 3);
    combine4wt_k<<<ceil_div(1048576/4, 256), 256>>>(
        p_part, conv1_b, p_c1, p_w2, 16, 128, 128, 1048576);

    // conv2: 64->64 @64². grid (64,8,4)=2048
    convpart_k<64,64,64,1,4,16><<<dim3(64, 8, 4), 64>>>(
        p_w2, conv2_w, p_part, 64, 64, 16);
    combine4wt_k<<<ceil_div(1048576/4, 256), 256>>>(
        p_part, conv2_b, p_c2, p_w3, 64, 64, 64, 1048576);

    // conv3: 256->256 @32². grid (16,32,4)=2048
    convpart_k<32,32,64,1,4,16><<<dim3(16, 32, 4), 64>>>(
        p_w3, conv3_w, p_part, 256, 256, 64);
    combine4wt_k<<<ceil_div(1048576/4, 256), 256>>>(
        p_part, conv3_b, p_c3, p_w4, 256, 32, 32, 1048576);

    // bottleneck: three conv4 1024->1024 @16². grid (4,128,4)=2048
    convpart_k<16,16,64,1,4,16><<<dim3(4, 128, 4), 64>>>(
        p_w4, conv4_w, p_part, 1024, 1024, 256);
    combine4_k<true,false><<<ceil_div(1048576/2, 256), 256>>>(
        p_part, conv4_b, nullptr, p_c4, 1024, 16*16, 1048576);
    convpart_k<16,16,64,1,4,16><<<dim3(4, 128, 4), 64>>>(
        p_c4, conv4_w, p_part, 1024, 1024, 256);
    combine4_k<true,false><<<ceil_div(1048576/2, 256), 256>>>(
        p_part, conv4_b, nullptr, p_c5, 1024, 16*16, 1048576);
    convpart_k<16,16,64,1,4,16><<<dim3(4, 128, 4), 64>>>(
        p_c5, conv4_w, p_part, 1024, 1024, 256);
    combine4_k<true,true><<<ceil_div(1048576/2, 256), 256>>>(
        p_part, conv4_b, p_w4, p_ic4, 1024, 16*16, 1048576);

    // decoder — fused iwt + skip concat
    iwtcat_k<<<ceil_div(4*256*16*16 + 4*256*2*16*16*2, 256), 256>>>(
        p_ic4, p_c3, p_iw4, 4, 1024, 16, 16, 512);

    // convd4: 512->256 @32². grid (16,32,4)=2048
    convpart_k<32,32,64,1,4,16><<<dim3(16, 32, 4), 64>>>(
        p_iw4, convd4_w, p_part, 512, 256, 128);
    combine4_k<true,false><<<ceil_div(1048576/2, 256), 256>>>(
        p_part, convd4_b, nullptr, p_ic3, 256, 32*32, 1048576);

    iwtcat_k<<<ceil_div(4*64*32*32 + 4*64*2*32*32*2, 256), 256>>>(
        p_ic3, p_c2, p_iw3, 4, 256, 32, 32, 128);

    // convd3: 128->64 @64². grid (64,8,4)=2048
    convpart_k<64,64,64,1,4,16><<<dim3(64, 8, 4), 64>>>(
        p_iw3, convd3_w, p_part, 128, 64, 32);
    combine4_k<true,false><<<ceil_div(1048576/2, 256), 256>>>(
        p_part, convd3_b, nullptr, p_ic2, 64, 64*64, 1048576);

    iwtcat_k<<<ceil_div(4*16*64*64 + 4*16*2*64*64*2, 256), 256>>>(
        p_ic2, p_c1, p_iw2, 4, 64, 64, 64, 32);

    // convd2: 32->16 @128². grid (256,2,4)=2048
    convpart_k<128,128,64,1,4,8><<<dim3(256, 2, 4), 64>>>(
        p_iw2, convd2_w, p_part, 32, 16, 8);
    combine4_k<true,false><<<ceil_div(1048576/2, 256), 256>>>(
        p_part, convd2_b, nullptr, p_ic1, 16, 128*128, 1048576);

    // convd1: 16->12 @128². NP=3 (OCBLK=6). grid (256,2,4)=2048
    convpart_k<128,128,64,1,3,4><<<dim3(256, 2, 4), 64>>>(
        p_ic1, convd1_w, p_part, 16, 12, 4);
    combine4_k<true,false><<<ceil_div(786432/2, 256), 256>>>(
        p_part, convd1_b, nullptr, p_iw1, 12, 128*128, 786432);

    // fused final iwt + 1x1
    final_k<<<ceil_div(4*128*128, 256), 256>>>(p_iw1, cfin_w, out, 4);
}

// round 14
// speedup vs baseline: 1.2494x; 1.0104x over previous
#include <cuda_runtime.h>
#include <cstdint>

typedef unsigned long long ull;

// ---------------------------------------------------------------------------
// Scratch buffers (device globals; no allocation allowed)
// ---------------------------------------------------------------------------
__device__ float g_w1 [786432];    // [4,12,128,128]
__device__ float g_c1 [1048576];   // [4,16,128,128]
__device__ float g_w2 [1048576];   // [4,64,64,64]
__device__ float g_c2 [1048576];   // [4,64,64,64]
__device__ float g_w3 [1048576];   // [4,256,32,32]
__device__ float g_c3 [1048576];   // [4,256,32,32]
__device__ float g_w4 [1048576];   // [4,1024,16,16]
__device__ float g_c4 [1048576];
__device__ float g_c5 [1048576];
__device__ float g_ic4[1048576];
__device__ float g_iw4[2097152];   // [4,512,32,32]
__device__ float g_ic3[1048576];   // [4,256,32,32]
__device__ float g_iw3[2097152];   // [4,128,64,64]
__device__ float g_ic2[1048576];   // [4,64,64,64]
__device__ float g_iw2[2097152];   // [4,32,128,128]
__device__ float g_ic1[1048576];   // [4,16,128,128]
__device__ float g_iw1[786432];    // [4,12,128,128]
__device__ float g_part[4194304];  // 4 x 1M partial-sum buffers
__device__ float2 g_wpk[4718592];  // packed weights [IC*9][OC/2] (max: conv4)

// ---------------------------------------------------------------------------
// f32x2 packed helpers (Blackwell FFMA2)
// ---------------------------------------------------------------------------
__device__ __forceinline__ ull pk(float x, float y) {
    ull r;
    asm("mov.b64 %0, {%1, %2};" : "=l"(r) : "f"(x), "f"(y));
    return r;
}
__device__ __forceinline__ void upk(float& x, float& y, ull v) {
    asm("mov.b64 {%0, %1}, %2;" : "=f"(x), "=f"(y) : "l"(v));
}
__device__ __forceinline__ void fma2(ull& d, ull a, ull b) {
    asm("fma.rn.f32x2 %0, %1, %2, %0;" : "+l"(d) : "l"(a), "l"(b));
}

// ---------------------------------------------------------------------------
// Weight pre-pack: w[OC][IC][9] -> wpk[t9][ocpair] with t9 = ic*9+t.
// Reads coalesced along t9 (contiguous within an oc row).
// ---------------------------------------------------------------------------
__global__ void packw_k(const float* __restrict__ w, float2* __restrict__ wpk,
                        int OCp, int IC9) {
    int i = blockIdx.x * blockDim.x + threadIdx.x;
    int total = OCp * IC9;
    if (i >= total) return;
    int p  = i / IC9;
    int t9 = i - p * IC9;
    float a = w[(size_t)(2 * p) * IC9 + t9];
    float b = w[(size_t)(2 * p + 1) * IC9 + t9];
    wpk[(size_t)t9 * OCp + p] = make_float2(a, b);
}

// ---------------------------------------------------------------------------
// Haar DWT (standalone — only for the network input x)
// ---------------------------------------------------------------------------
__global__ void wt_k(const float* __restrict__ in, float* __restrict__ out,
                     int B, int C, int H, int W) {
    int Ho = H >> 1, Wo = W >> 1;
    int total = B * C * Ho * Wo;
    int i = blockIdx.x * blockDim.x + threadIdx.x;
    if (i >= total) return;
    int w = i % Wo;
    int h = (i / Wo) % Ho;
    int c = (i / (Wo * Ho)) % C;
    int b = i / (Wo * Ho * C);
    const float* p = in + ((size_t)(b * C + c) * H + 2 * h) * W + 2 * w;
    float a  = p[0], bb = p[1], cc = p[W], d = p[W + 1];
    float ll = 0.25f * (a + bb + cc + d);
    float hl = 0.5f  * (a + bb - cc - d);
    float lh = 0.5f  * (a - bb + cc - d);
    float hh = 0.5f  * (a - bb - cc + d);
    size_t ob = ((size_t)(b * 4 * C + 4 * c) * Ho + h) * Wo + w;
    size_t cs = (size_t)Ho * Wo;
    out[ob]          = ll;
    out[ob + cs]     = (hl + 1.f) * 0.5f;
    out[ob + 2 * cs] = (lh + 1.f) * 0.5f;
    out[ob + 3 * cs] = (hh + 1.f) * 0.5f;
}

// ---------------------------------------------------------------------------
// Fused IWT + skip-concat:  out[:, :Csrc] = skip;  out[:, Csrc:] = iwt(iwin)
// ---------------------------------------------------------------------------
__global__ void iwtcat_k(const float* __restrict__ iwin, const float* __restrict__ skip,
                         float* __restrict__ out, int B, int C4, int H, int W, int Ctot) {
    int C = C4 >> 2;
    int Csrc = Ctot - C;
    int HWo = 4 * H * W;
    int Niwt = B * C * H * W;
    int npc = HWo / 2;
    int Ncopy2 = B * Csrc * npc;
    int i = blockIdx.x * blockDim.x + threadIdx.x;
    if (i < Niwt) {
        int w = i % W;
        int h = (i / W) % H;
        int c = (i / (W * H)) % C;
        int b = i / (W * H * C);
        size_t ib = ((size_t)(b * C4 + 4 * c) * H + h) * W + w;
        size_t cs = (size_t)H * W;
        float v0 = iwin[ib];
        float v1 = 2.f * iwin[ib + cs]     - 1.f;
        float v2 = 2.f * iwin[ib + 2 * cs] - 1.f;
        float v3 = 2.f * iwin[ib + 3 * cs] - 1.f;
        float x00 = v0 + 0.5f * ( v1 + v2 + v3);
        float x01 = v0 + 0.5f * ( v1 - v2 - v3);
        float x10 = v0 + 0.5f * (-v1 + v2 - v3);
        float x11 = v0 + 0.5f * (-v1 - v2 + v3);
        int W2 = 2 * W;
        size_t ob = ((size_t)(b * Ctot + Csrc + c) * 2 * H + 2 * h) * W2 + 2 * w;
        out[ob]          = x00;
        out[ob + 1]      = x01;
        out[ob + W2]     = x10;
        out[ob + W2 + 1] = x11;
    } else {
        int j = i - Niwt;
        if (j >= Ncopy2) return;
        int pos = j % npc;
        int c   = (j / npc) % Csrc;
        int b   = j / (npc * Csrc);
        *(float2*)&out[((size_t)(b * Ctot) + c) * HWo + 2 * pos] =
            *(const float2*)&skip[((size_t)(b * Csrc) + c) * HWo + 2 * pos];
    }
}

// ---------------------------------------------------------------------------
// Partial direct 3x3 conv, pad=1 — oc-pair lane packing, 2x2 px per thread.
// Pre-packed weights streamed straight into smem (no re-pack, 1 barrier/chunk).
// NP oc-pairs per thread, explicit per-thread input double-buffer.
// 64-thread blocks for high residency. blockIdx.z selects IC split.
// ---------------------------------------------------------------------------
template <int H, int W, int TPX, int NP, int ICCHUNK>
__global__ void __launch_bounds__(TPX, 10)
convpart_k(const float* __restrict__ in, const float2* __restrict__ wpk,
           float* __restrict__ part, int IC, int OC, int ics) {
    constexpr int NT = TPX;
    constexpr int OCBLK = 2 * NP;
    constexpr int DN = ICCHUNK * 9 * NP;   // packed float2 per chunk
    constexpr int TILESIMG = (H / 2) * (W / 2);

    __shared__ __align__(16) float2 s_pk[2][DN];

    const int tid = threadIdx.x;
    const int g   = blockIdx.x * TPX + tid;
    const int img = g / TILESIMG;
    const int rem = g % TILESIMG;
    const int h0  = (rem / (W / 2)) * 2;
    const int w0  = (rem % (W / 2)) * 2;
    const int ocp0 = blockIdx.y * NP;     // pair offset
    const int OCp  = OC >> 1;
    const int z   = blockIdx.z;
    const int ic0 = z * ics;

    const size_t HW = (size_t)H * W;
    const bool vr0 = (h0 > 0);
    const bool vr3 = (h0 + 2 < H);
    const bool lok = (w0 > 0);
    const bool rok = (w0 + 2 < W);

    ull acc[NP][2][2];
#pragma unroll
    for (int np = 0; np < NP; np++)
#pragma unroll
        for (int r = 0; r < 2; r++)
#pragma unroll
            for (int c = 0; c < 2; c++) acc[np][r][c] = pk(0.f, 0.f);

    const float* p0 = in + ((size_t)img * IC + ic0) * HW + (size_t)(h0 - 1) * W + (w0 - 1);
    const int nch = ics / ICCHUNK;

    // chunk loader: packed rows R = (ic0 + c*ICCHUNK)*9 + r, NP float2 each
    auto load_chunk = [&](int c, int buf) {
        const float2* srcbase = wpk + ((size_t)(ic0 + c * ICCHUNK) * 9) * OCp + ocp0;
        if constexpr ((NP % 2) == 0) {
            for (int i = tid; i < DN / 2; i += NT) {
                int r = i / (NP / 2);
                int q = (i - r * (NP / 2)) * 2;
                const float2* src = srcbase + (size_t)r * OCp + q;
                uint32_t dst = (uint32_t)__cvta_generic_to_shared(&s_pk[buf][r * NP + q]);
                asm volatile("cp.async.ca.shared.global [%0], [%1], 16;" :: "r"(dst), "l"(src));
            }
        } else {
            for (int i = tid; i < DN; i += NT) {
                int r = i / NP;
                int q = i - r * NP;
                const float2* src = srcbase + (size_t)r * OCp + q;
                uint32_t dst = (uint32_t)__cvta_generic_to_shared(&s_pk[buf][r * NP + q]);
                asm volatile("cp.async.ca.shared.global [%0], [%1], 8;" :: "r"(dst), "l"(src));
            }
        }
    };

    load_chunk(0, 0);
    asm volatile("cp.async.commit_group;" ::: "memory");

    float cl[2][4], cx[2][4], cy[2][4], cr[2][4];

    for (int ch = 0; ch < nch; ch++) {
        asm volatile("cp.async.wait_group 0;" ::: "memory");
        __syncthreads();
        if (ch + 1 < nch) load_chunk(ch + 1, (ch + 1) & 1);
        asm volatile("cp.async.commit_group;" ::: "memory");

        const float2* wchunk = s_pk[ch & 1];
        const float* pb = p0 + (size_t)(ch * ICCHUNK) * HW;
        // load ic 0 of chunk into buffer 0
#pragma unroll
        for (int ri = 0; ri < 4; ri++) {
            bool vr = (ri == 0) ? vr0 : (ri == 3) ? vr3 : true;
            const float* q = pb + ri * W;
            float2 m = make_float2(0.f, 0.f);
            float l = 0.f, r = 0.f;
            if (vr) {
                m = *(const float2*)(q + 1);
                if (lok) l = q[0];
                if (rok) r = q[3];
            }
            cl[0][ri] = l; cx[0][ri] = m.x; cy[0][ri] = m.y; cr[0][ri] = r;
        }

#pragma unroll 2
        for (int kk = 0; kk < ICCHUNK; kk++) {
            const int cb = kk & 1;
            // prefetch next ic
            if (kk + 1 < ICCHUNK) {
                const float* pn = pb + (size_t)(kk + 1) * HW;
#pragma unroll
                for (int ri = 0; ri < 4; ri++) {
                    bool vr = (ri == 0) ? vr0 : (ri == 3) ? vr3 : true;
                    const float* q = pn + ri * W;
                    float2 m = make_float2(0.f, 0.f);
                    float l = 0.f, r = 0.f;
                    if (vr) {
                        m = *(const float2*)(q + 1);
                        if (lok) l = q[0];
                        if (rok) r = q[3];
                    }
                    cl[cb ^ 1][ri] = l; cx[cb ^ 1][ri] = m.x;
                    cy[cb ^ 1][ri] = m.y; cr[cb ^ 1][ri] = r;
                }
            }
            // broadcast-pack current ic
            ull bp[4][4];
#pragma unroll
            for (int ri = 0; ri < 4; ri++) {
                bp[ri][0] = pk(cl[cb][ri], cl[cb][ri]);
                bp[ri][1] = pk(cx[cb][ri], cx[cb][ri]);
                bp[ri][2] = pk(cy[cb][ri], cy[cb][ri]);
                bp[ri][3] = pk(cr[cb][ri], cr[cb][ri]);
            }
            const float2* wrow = wchunk + kk * 9 * NP;
#pragma unroll
            for (int ki = 0; ki < 3; ki++)
#pragma unroll
                for (int kj = 0; kj < 3; kj++) {
                    const int t = ki * 3 + kj;
                    ull wv[NP];
                    if constexpr ((NP % 2) == 0) {
#pragma unroll
                        for (int q2 = 0; q2 < NP / 2; q2++) {
                            ulonglong2 u = *(const ulonglong2*)&wrow[t * NP + 2 * q2];
                            wv[2 * q2]     = u.x;
                            wv[2 * q2 + 1] = u.y;
                        }
                    } else {
#pragma unroll
                        for (int np = 0; np < NP; np++)
                            wv[np] = *(const ull*)&wrow[t * NP + np];
                    }
#pragma unroll
                    for (int np = 0; np < NP; np++) {
                        fma2(acc[np][0][0], bp[ki][kj],         wv[np]);
                        fma2(acc[np][0][1], bp[ki][kj + 1],     wv[np]);
                        fma2(acc[np][1][0], bp[ki + 1][kj],     wv[np]);
                        fma2(acc[np][1][1], bp[ki + 1][kj + 1], wv[np]);
                    }
                }
        }
    }

    // ---- store raw partials ----
    float* pout = part + (size_t)z * 4 * OC * HW;
#pragma unroll
    for (int np = 0; np < NP; np++) {
        float a00, b00, a01, b01, a10, b10, a11, b11;
        upk(a00, b00, acc[np][0][0]); upk(a01, b01, acc[np][0][1]);
        upk(a10, b10, acc[np][1][0]); upk(a11, b11, acc[np][1][1]);
        const int ocA = 2 * (ocp0 + np);
        size_t baseA = ((size_t)(img * OC + ocA) * H + h0) * W + w0;
        size_t baseB = baseA + HW;
        *(float2*)&pout[baseA]     = make_float2(a00, a01);
        *(float2*)&pout[baseA + W] = make_float2(a10, a11);
        *(float2*)&pout[baseB]     = make_float2(b00, b01);
        *(float2*)&pout[baseB + W] = make_float2(b10, b11);
    }
}

// ---------------------------------------------------------------------------
// Combine four partial buffers: out = act(p0+p1+p2+p3 + bias (+skip))
// ---------------------------------------------------------------------------
template <bool RELU, bool ADD>
__global__ void combine4_k(const float* __restrict__ part, const float* __restrict__ bias,
                           const float* __restrict__ addsrc, float* __restrict__ out,
                           int OC, int HW, int total) {
    int i = (blockIdx.x * blockDim.x + threadIdx.x) * 2;
    if (i >= total) return;
    int c = (i / HW) % OC;
    float2 p0 = *(const float2*)&part[i];
    float2 p1 = *(const float2*)&part[total + i];
    float2 p2 = *(const float2*)&part[2 * (size_t)total + i];
    float2 p3 = *(const float2*)&part[3 * (size_t)total + i];
    float bv = bias[c];
    float v0 = (p0.x + p1.x) + (p2.x + p3.x) + bv;
    float v1 = (p0.y + p1.y) + (p2.y + p3.y) + bv;
    if (ADD) {
        float2 s = *(const float2*)&addsrc[i];
        v0 += s.x; v1 += s.y;
    }
    if (RELU) {
        v0 = (v0 >= 0.f) ? v0 : 0.2f * v0;
        v1 = (v1 >= 0.f) ? v1 : 0.2f * v1;
    }
    *(float2*)&out[i] = make_float2(v0, v1);
}

// ---------------------------------------------------------------------------
// Combine four partials + lrelu + fused Haar DWT of the result.
// ---------------------------------------------------------------------------
__global__ void combine4wt_k(const float* __restrict__ part, const float* __restrict__ bias,
                             float* __restrict__ out, float* __restrict__ wtout,
                             int OC, int H, int W, int total) {
    int HW = H * W;
    int nblk = total / 4;
    int i = blockIdx.x * blockDim.x + threadIdx.x;
    if (i >= nblk) return;
    int Wh = W / 2;
    int w2 = i % Wh;
    int h2 = (i / Wh) % (H / 2);
    int bc = i / (HW / 4);
    size_t base = (size_t)bc * HW + (size_t)(2 * h2) * W + 2 * w2;
    float bv = bias[bc % OC];
    float v00 = bv, v01 = bv, v10 = bv, v11 = bv;
#pragma unroll
    for (int z = 0; z < 4; z++) {
        const float* p = part + (size_t)z * total;
        float2 a = *(const float2*)&p[base];
        float2 b = *(const float2*)&p[base + W];
        v00 += a.x; v01 += a.y; v10 += b.x; v11 += b.y;
    }
    v00 = (v00 >= 0.f) ? v00 : 0.2f * v00;
    v01 = (v01 >= 0.f) ? v01 : 0.2f * v01;
    v10 = (v10 >= 0.f) ? v10 : 0.2f * v10;
    v11 = (v11 >= 0.f) ? v11 : 0.2f * v11;
    *(float2*)&out[base]     = make_float2(v00, v01);
    *(float2*)&out[base + W] = make_float2(v10, v11);

    float ll = 0.25f * (v00 + v01 + v10 + v11);
    float hl = 0.5f  * (v00 + v01 - v10 - v11);
    float lh = 0.5f  * (v00 - v01 + v10 - v11);
    float hh = 0.5f  * (v00 - v01 - v10 + v11);
    hl = (hl + 1.f) * 0.5f; lh = (lh + 1.f) * 0.5f; hh = (hh + 1.f) * 0.5f;
    int c = bc % OC, b_ = bc / OC;
    size_t cs = (size_t)HW / 4;
    size_t ob = ((size_t)(b_ * 4 * OC + 4 * c)) * cs + (size_t)h2 * Wh + w2;
    wtout[ob]          = ll;
    wtout[ob + cs]     = hl;
    wtout[ob + 2 * cs] = lh;
    wtout[ob + 3 * cs] = hh;
}

// ---------------------------------------------------------------------------
// Final: y = iwt(iw1[4,12,128,128]); out = 1x1 conv cfin @ y -> [4,3,256,256]
// ---------------------------------------------------------------------------
__global__ void final_k(const float* __restrict__ in, const float* __restrict__ cfin,
                        float* __restrict__ out, int B) {
    const int H = 128, W = 128;
    int total = B * H * W;
    int i = blockIdx.x * blockDim.x + threadIdx.x;
    if (i >= total) return;
    int w = i % W;
    int h = (i / W) % H;
    int b = i / (W * H);

    float y00[3], y01[3], y10[3], y11[3];
#pragma unroll
    for (int c = 0; c < 3; c++) {
        size_t ib = ((size_t)(b * 12 + 4 * c) * H + h) * W + w;
        size_t cs = (size_t)H * W;
        float v0 = in[ib];
        float v1 = 2.f * in[ib + cs]     - 1.f;
        float v2 = 2.f * in[ib + 2 * cs] - 1.f;
        float v3 = 2.f * in[ib + 3 * cs] - 1.f;
        y00[c] = v0 + 0.5f * ( v1 + v2 + v3);
        y01[c] = v0 + 0.5f * ( v1 - v2 - v3);
        y10[c] = v0 + 0.5f * (-v1 + v2 - v3);
        y11[c] = v0 + 0.5f * (-v1 - v2 + v3);
    }
    float m[9];
#pragma unroll
    for (int j = 0; j < 9; j++) m[j] = cfin[j];

    const int HO = 256, WO = 256;
#pragma unroll
    for (int o = 0; o < 3; o++) {
        float o00 = m[o*3+0]*y00[0] + m[o*3+1]*y00[1] + m[o*3+2]*y00[2];
        float o01 = m[o*3+0]*y01[0] + m[o*3+1]*y01[1] + m[o*3+2]*y01[2];
        float o10 = m[o*3+0]*y10[0] + m[o*3+1]*y10[1] + m[o*3+2]*y10[2];
        float o11 = m[o*3+0]*y11[0] + m[o*3+1]*y11[1] + m[o*3+2]*y11[2];
        size_t ob = ((size_t)(b * 3 + o) * HO + 2 * h) * WO + 2 * w;
        out[ob]          = o00;
        out[ob + 1]      = o01;
        out[ob + WO]     = o10;
        out[ob + WO + 1] = o11;
    }
}

// ---------------------------------------------------------------------------
// Host side
// ---------------------------------------------------------------------------
static inline int ceil_div(int a, int b) { return (a + b - 1) / b; }

extern "C" void kernel_launch(void* const* d_in, const int* in_sizes, int n_in,
                              void* d_out, int out_size) {
    (void)in_sizes; (void)n_in; (void)out_size;
    const float* x        = (const float*)d_in[0];
    const float* conv1_w  = (const float*)d_in[1];
    const float* conv1_b  = (const float*)d_in[2];
    const float* conv2_w  = (const float*)d_in[3];
    const float* conv2_b  = (const float*)d_in[4];
    const float* conv3_w  = (const float*)d_in[5];
    const float* conv3_b  = (const float*)d_in[6];
    const float* conv4_w  = (const float*)d_in[7];
    const float* conv4_b  = (const float*)d_in[8];
    const float* convd4_w = (const float*)d_in[9];
    const float* convd4_b = (const float*)d_in[10];
    const float* convd3_w = (const float*)d_in[11];
    const float* convd3_b = (const float*)d_in[12];
    const float* convd2_w = (const float*)d_in[13];
    const float* convd2_b = (const float*)d_in[14];
    const float* convd1_w = (const float*)d_in[15];
    const float* convd1_b = (const float*)d_in[16];
    const float* cfin_w   = (const float*)d_in[17];
    float* out = (float*)d_out;

    static float *p_w1=nullptr,*p_c1,*p_w2,*p_c2,*p_w3,*p_c3,*p_w4,*p_c4,*p_c5,
                 *p_ic4,*p_iw4,*p_ic3,*p_iw3,*p_ic2,*p_iw2,*p_ic1,*p_iw1,*p_part;
    static float2 *p_wpk;
    if (!p_w1) {
        cudaGetSymbolAddress((void**)&p_w1,  g_w1);
        cudaGetSymbolAddress((void**)&p_c1,  g_c1);
        cudaGetSymbolAddress((void**)&p_w2,  g_w2);
        cudaGetSymbolAddress((void**)&p_c2,  g_c2);
        cudaGetSymbolAddress((void**)&p_w3,  g_w3);
        cudaGetSymbolAddress((void**)&p_c3,  g_c3);
        cudaGetSymbolAddress((void**)&p_w4,  g_w4);
        cudaGetSymbolAddress((void**)&p_c4,  g_c4);
        cudaGetSymbolAddress((void**)&p_c5,  g_c5);
        cudaGetSymbolAddress((void**)&p_ic4, g_ic4);
        cudaGetSymbolAddress((void**)&p_iw4, g_iw4);
        cudaGetSymbolAddress((void**)&p_ic3, g_ic3);
        cudaGetSymbolAddress((void**)&p_iw3, g_iw3);
        cudaGetSymbolAddress((void**)&p_ic2, g_ic2);
        cudaGetSymbolAddress((void**)&p_iw2, g_iw2);
        cudaGetSymbolAddress((void**)&p_ic1, g_ic1);
        cudaGetSymbolAddress((void**)&p_iw1, g_iw1);
        cudaGetSymbolAddress((void**)&p_part, g_part);
        cudaGetSymbolAddress((void**)&p_wpk, g_wpk);
    }

    auto packw = [&](const float* w, int OC, int IC) {
        int OCp = OC / 2, IC9 = IC * 9;
        packw_k<<<ceil_div(OCp * IC9, 256), 256>>>(w, p_wpk, OCp, IC9);
    };

    // w1 = wt(x)
    wt_k<<<ceil_div(4*3*128*128, 256), 256>>>(x, p_w1, 4, 3, 256, 256);

    // conv1: 12->16 @128². 64thr, OCBLK=8, S=4. grid (256,2,4)=2048
    packw(conv1_w, 16, 12);
    convpart_k<128,128,64,4,3><<<dim3(256, 2, 4), 64>>>(
        p_w1, p_wpk, p_part, 12, 16, 3);
    combine4wt_k<<<ceil_div(1048576/4, 256), 256>>>(
        p_part, conv1_b, p_c1, p_w2, 16, 128, 128, 1048576);

    // conv2: 64->64 @64². grid (64,8,4)=2048
    packw(conv2_w, 64, 64);
    convpart_k<64,64,64,4,16><<<dim3(64, 8, 4), 64>>>(
        p_w2, p_wpk, p_part, 64, 64, 16);
    combine4wt_k<<<ceil_div(1048576/4, 256), 256>>>(
        p_part, conv2_b, p_c2, p_w3, 64, 64, 64, 1048576);

    // conv3: 256->256 @32². grid (16,32,4)=2048
    packw(conv3_w, 256, 256);
    convpart_k<32,32,64,4,16><<<dim3(16, 32, 4), 64>>>(
        p_w3, p_wpk, p_part, 256, 256, 64);
    combine4wt_k<<<ceil_div(1048576/4, 256), 256>>>(
        p_part, conv3_b, p_c3, p_w4, 256, 32, 32, 1048576);

    // bottleneck: three conv4 1024->1024 @16². grid (4,128,4)=2048
    packw(conv4_w, 1024, 1024);
    convpart_k<16,16,64,4,16><<<dim3(4, 128, 4), 64>>>(
        p_w4, p_wpk, p_part, 1024, 1024, 256);
    combine4_k<true,false><<<ceil_div(1048576/2, 256), 256>>>(
        p_part, conv4_b, nullptr, p_c4, 1024, 16*16, 1048576);
    convpart_k<16,16,64,4,16><<<dim3(4, 128, 4), 64>>>(
        p_c4, p_wpk, p_part, 1024, 1024, 256);
    combine4_k<true,false><<<ceil_div(1048576/2, 256), 256>>>(
        p_part, conv4_b, nullptr, p_c5, 1024, 16*16, 1048576);
    convpart_k<16,16,64,4,16><<<dim3(4, 128, 4), 64>>>(
        p_c5, p_wpk, p_part, 1024, 1024, 256);
    combine4_k<true,true><<<ceil_div(1048576/2, 256), 256>>>(
        p_part, conv4_b, p_w4, p_ic4, 1024, 16*16, 1048576);

    // decoder — fused iwt + skip concat
    iwtcat_k<<<ceil_div(4*256*16*16 + 4*256*2*16*16*2, 256), 256>>>(
        p_ic4, p_c3, p_iw4, 4, 1024, 16, 16, 512);

    // convd4: 512->256 @32². grid (16,32,4)=2048
    packw(convd4_w, 256, 512);
    convpart_k<32,32,64,4,16><<<dim3(16, 32, 4), 64>>>(
        p_iw4, p_wpk, p_part, 512, 256, 128);
    combine4_k<true,false><<<ceil_div(1048576/2, 256), 256>>>(
        p_part, convd4_b, nullptr, p_ic3, 256, 32*32, 1048576);

    iwtcat_k<<<ceil_div(4*64*32*32 + 4*64*2*32*32*2, 256), 256>>>(
        p_ic3, p_c2, p_iw3, 4, 256, 32, 32, 128);

    // convd3: 128->64 @64². grid (64,8,4)=2048
    packw(convd3_w, 64, 128);
    convpart_k<64,64,64,4,16><<<dim3(64, 8, 4), 64>>>(
        p_iw3, p_wpk, p_part, 128, 64, 32);
    combine4_k<true,false><<<ceil_div(1048576/2, 256), 256>>>(
        p_part, convd3_b, nullptr, p_ic2, 64, 64*64, 1048576);

    iwtcat_k<<<ceil_div(4*16*64*64 + 4*16*2*64*64*2, 256), 256>>>(
        p_ic2, p_c1, p_iw2, 4, 64, 64, 64, 32);

    // convd2: 32->16 @128². grid (256,2,4)=2048
    packw(convd2_w, 16, 32);
    convpart_k<128,128,64,4,8><<<dim3(256, 2, 4), 64>>>(
        p_iw2, p_wpk, p_part, 32, 16, 8);
    combine4_k<true,false><<<ceil_div(1048576/2, 256), 256>>>(
        p_part, convd2_b, nullptr, p_ic1, 16, 128*128, 1048576);

    // convd1: 16->12 @128². NP=3 (OCBLK=6). grid (256,2,4)=2048
    packw(convd1_w, 12, 16);
    convpart_k<128,128,64,3,4><<<dim3(256, 2, 4), 64>>>(
        p_ic1, p_wpk, p_part, 16, 12, 4);
    combine4_k<true,false><<<ceil_div(786432/2, 256), 256>>>(
        p_part, convd1_b, nullptr, p_iw1, 12, 128*128, 786432);

    // fused final iwt + 1x1
    final_k<<<ceil_div(4*128*128, 256), 256>>>(p_iw1, cfin_w, out, 4);
}